// round 15
// baseline (speedup 1.0000x reference)
#include <cuda_runtime.h>
#include <cuda_bf16.h>
#include <math.h>
#include <stdint.h>

#define NE 16384
#define NNODES 1024
#define PI_D 3.14159265358979323846

// ---------------- scratch ----------------
__device__ float    g_cg[573];
__device__ float    g_actc;
__device__ float    g_node[NNODES * 64 * 16];
__device__ float    g_d[NE];
__device__ float    g_w[NE * 64];
__device__ float    g_Yt[NE * 16];
__device__ __align__(16) uint32_t g_hp[NE * 256];       // packed MLP input [e][k]
__device__ __align__(16) uint32_t g_V1p[NE * 3 * 320];  // packed (hi bf16 | lo bf16<<16), row=(e*3+i), K=320
__device__ __align__(16) uint32_t g_V2p[NE * 5 * 320];  // row=(e*5+k)
__device__ __align__(16) uint32_t g_WvBh1[64 * 160];
__device__ __align__(16) uint32_t g_WvBl1[64 * 160];
__device__ __align__(16) uint32_t g_WvBh2[64 * 160];
__device__ __align__(16) uint32_t g_WvBl2[64 * 160];
__device__ __align__(16) uint32_t g_W1h[64 * 128];
__device__ __align__(16) uint32_t g_W1l[64 * 128];
__device__ __align__(16) uint32_t g_W2h[64 * 32];
__device__ __align__(16) uint32_t g_W2l[64 * 32];
__device__ __align__(16) uint32_t g_W3h[64 * 32];
__device__ __align__(16) uint32_t g_W3l[64 * 32];
__device__ __align__(16) uint32_t g_Wwh[64 * 32];
__device__ __align__(16) uint32_t g_Wwl[64 * 32];
__device__ int      g_cnt[NNODES];      // zero-init at load; k_scan re-zeroes after read
__device__ int      g_off[NNODES + 1];
__device__ int      g_cur[NNODES];
__device__ int      g_eidx[NE];

// ---------------- device helpers ----------------
__device__ __forceinline__ uint32_t pack_hl(float v){
    __nv_bfloat16 h = __float2bfloat16(v);
    float hf = __bfloat162float(h);
    __nv_bfloat16 l = __float2bfloat16(v - hf);
    return (uint32_t)__bfloat16_as_ushort(h) | ((uint32_t)__bfloat16_as_ushort(l) << 16);
}
__device__ __forceinline__ void split2(float v0, float v1, uint32_t& h, uint32_t& l){
    uint32_t p0 = pack_hl(v0), p1 = pack_hl(v1);
    h = __byte_perm(p0, p1, 0x5410);
    l = __byte_perm(p0, p1, 0x7632);
}
__device__ __forceinline__ void mma16816(float* d,
        uint32_t a0, uint32_t a1, uint32_t a2, uint32_t a3,
        uint32_t b0, uint32_t b1){
    asm volatile(
        "mma.sync.aligned.m16n8k16.row.col.f32.bf16.bf16.f32 "
        "{%0,%1,%2,%3}, {%4,%5,%6,%7}, {%8,%9}, {%0,%1,%2,%3};"
        : "+f"(d[0]), "+f"(d[1]), "+f"(d[2]), "+f"(d[3])
        : "r"(a0), "r"(a1), "r"(a2), "r"(a3), "r"(b0), "r"(b1));
}

// ---------------- host-side CG + ACT_C ----------------
static const int h_l1[13]  = {0,1,2, 0,1,1,2,3, 0,1,2,2,3};
static const int h_l2[13]  = {0,1,2, 1,0,2,1,2, 2,1,0,2,1};
static const int h_l3[13]  = {0,0,0, 1,1,1,1,1, 2,2,2,2,2};
static const int h_offs[14]= {0,1,10,35,44,53,98,143,248,273,318,343,468,573};

static double h_dfact(int n){ double r=1.0; while(n>1){ r*=(double)n; n-=2; } return r; }
static double h_mono(int a,int b,int c){
    if((a&1)||(b&1)||(c&1)) return 0.0;
    return 4.0*PI_D*h_dfact(a-1)*h_dfact(b-1)*h_dfact(c-1)/h_dfact(a+b+c+1);
}
static int h_sh(int l,int m,double* c,int (*ex)[3]){
    double S3=sqrt(3.0), S5=sqrt(5.0), S15=sqrt(15.0);
    double C33=sqrt(70.0)/4.0, C32=sqrt(105.0)/2.0, C31=sqrt(42.0)/4.0, C30=sqrt(7.0)/2.0, CX=sqrt(105.0);
#define TT(t,cc,a,b,cz) { c[t]=(cc); ex[t][0]=(a); ex[t][1]=(b); ex[t][2]=(cz); }
    if(l==0){ TT(0,1.0,0,0,0); return 1; }
    if(l==1){
        if(m==0){ TT(0,S3,1,0,0); } else if(m==1){ TT(0,S3,0,1,0); } else { TT(0,S3,0,0,1); }
        return 1;
    }
    if(l==2){
        switch(m){
            case 0: TT(0,S15,1,1,0); return 1;
            case 1: TT(0,S15,0,1,1); return 1;
            case 2: TT(0,1.5*S5,0,0,2); TT(1,-0.5*S5,0,0,0); return 2;
            case 3: TT(0,S15,1,0,1); return 1;
            default: TT(0,0.5*S15,2,0,0); TT(1,-0.5*S15,0,2,0); return 2;
        }
    }
    switch(m){
        case 0: TT(0,3.0*C33,2,1,0); TT(1,-C33,0,3,0); return 2;
        case 1: TT(0,CX,1,1,1); return 1;
        case 2: TT(0,5.0*C31,0,1,2); TT(1,-C31,0,1,0); return 2;
        case 3: TT(0,5.0*C30,0,0,3); TT(1,-3.0*C30,0,0,1); return 2;
        case 4: TT(0,5.0*C31,1,0,2); TT(1,-C31,1,0,0); return 2;
        case 5: TT(0,C32,2,0,1); TT(1,-C32,0,2,1); return 2;
        default: TT(0,C33,3,0,0); TT(1,-3.0*C33,1,2,0); return 2;
    }
#undef TT
}

static float s_cg_host[573];
static float s_actc_host;

static void host_compute_constants(){
    double raw[573];
    for(int p=0;p<13;p++){
        int l1=h_l1[p], l2=h_l2[p], l3=h_l3[p];
        int n1=2*l1+1, n2=2*l2+1, n3=2*l3+1;
        int off=h_offs[p];
        for(int i=0;i<n1;i++) for(int j=0;j<n2;j++) for(int k=0;k<n3;k++){
            double c1[2],c2[2],c3[2]; int e1[2][3],e2[2][3],e3[2][3];
            int t1=h_sh(l1,i,c1,e1), t2=h_sh(l2,j,c2,e2), t3=h_sh(l3,k,c3,e3);
            double v=0.0;
            for(int a=0;a<t1;a++) for(int b=0;b<t2;b++) for(int cc=0;cc<t3;cc++)
                v += c1[a]*c2[b]*c3[cc]*h_mono(e1[a][0]+e2[b][0]+e3[cc][0],
                                              e1[a][1]+e2[b][1]+e3[cc][1],
                                              e1[a][2]+e2[b][2]+e3[cc][2]);
            raw[off + (i*n2+j)*n3 + k] = v/(4.0*PI_D);
        }
        double s=0.0;
        for(int q=off;q<h_offs[p+1];q++) s += raw[q]*raw[q];
        double sc = sqrt((double)(2*l3+1))/sqrt(s);
        for(int q=off;q<h_offs[p+1];q++) s_cg_host[q] = (float)(raw[q]*sc);
    }
    double step = 24.0/200000.0, acc=0.0;
    for(int i=0;i<=200000;i++){
        double z = -12.0 + step*(double)i;
        double phi = exp(-0.5*z*z)*0.39894228040143267794;
        double sl = z/(1.0+exp(-z));
        acc += sl*sl*phi;
    }
    s_actc_host = (float)sqrt(acc*step);
}

// ---------------- merged prep: weight packing (blocks < 136) + per-edge (blocks >= 136) ----------------
#define PREP_WPACK_BLOCKS 136
__global__ void k_prep(const float* __restrict__ Wv1, const float* __restrict__ Wv2,
                       const float* __restrict__ W1,  const float* __restrict__ W2,
                       const float* __restrict__ W3,  const float* __restrict__ Ww,
                       const float* __restrict__ x,   const float* __restrict__ vec,
                       const int* __restrict__ senders){
    if(blockIdx.x < PREP_WPACK_BLOCKS){
        int i = blockIdx.x*256+threadIdx.x;
        const float* W; uint32_t *Bh, *Bl; int j, np;
        if(i < 10240){ W=Wv1; Bh=g_WvBh1; Bl=g_WvBl1; j=i; np=160; }
        else if(i < 20480){ W=Wv2; Bh=g_WvBh2; Bl=g_WvBl2; j=i-10240; np=160; }
        else if(i < 28672){ W=W1; Bh=g_W1h; Bl=g_W1l; j=i-20480; np=128; }
        else if(i < 30720){ W=W2; Bh=g_W2h; Bl=g_W2l; j=i-28672; np=32; }
        else if(i < 32768){ W=W3; Bh=g_W3h; Bl=g_W3l; j=i-30720; np=32; }
        else if(i < 34816){ W=Ww; Bh=g_Wwh; Bl=g_Wwl; j=i-32768; np=32; }
        else return;
        int n=j/np, p=j-n*np;
        uint32_t p0 = pack_hl(W[(2*p  )*64 + n]);
        uint32_t p1 = pack_hl(W[(2*p+1)*64 + n]);
        Bh[j] = __byte_perm(p0, p1, 0x5410);
        Bl[j] = __byte_perm(p0, p1, 0x7632);
        return;
    }
    int i = (blockIdx.x - PREP_WPACK_BLOCKS)*256 + threadIdx.x;   // over NE*64
    int e = i>>6, k = i&63;
    g_hp[e*256+k] = pack_hl(x[i]);
    if(k==0){
        atomicAdd(&g_cnt[senders[e]],1);
        float vx=vec[e*3+0], vy=vec[e*3+1], vz=vec[e*3+2];
        float d = sqrtf(vx*vx+vy*vy+vz*vz);
        g_d[e]=d;
        float X=vx/d, Y=vy/d, Z=vz/d;
        const float S3=1.7320508075688772f, S5=2.2360679774997896f, S15=3.8729833462074170f;
        const float C33=2.0916500663351889f, C32=5.1234753829797990f, C31=1.6201851746019651f;
        const float C30=1.3228756555322954f, CX=10.246950765959598f;
        float y[16];
        y[0]=1.f; y[1]=S3*X; y[2]=S3*Y; y[3]=S3*Z;
        y[4]=S15*X*Y; y[5]=S15*Y*Z; y[6]=0.5f*S5*(3.f*Z*Z-1.f); y[7]=S15*X*Z; y[8]=0.5f*S15*(X*X-Y*Y);
        y[9]=C33*Y*(3.f*X*X-Y*Y); y[10]=CX*X*Y*Z; y[11]=C31*Y*(5.f*Z*Z-1.f);
        y[12]=C30*Z*(5.f*Z*Z-3.f); y[13]=C31*X*(5.f*Z*Z-1.f); y[14]=C32*Z*(X*X-Y*Y); y[15]=C33*X*(X*X-3.f*Y*Y);
        float4* yp=(float4*)(g_Yt+e*16);
        yp[0]=make_float4(y[0],y[1],y[2],y[3]);
        yp[1]=make_float4(y[4],y[5],y[6],y[7]);
        yp[2]=make_float4(y[8],y[9],y[10],y[11]);
        yp[3]=make_float4(y[12],y[13],y[14],y[15]);
    }
}

// ---------------- CSR scan (+ self-reset of g_cnt) and fill ----------------
__global__ void k_scan(){
    __shared__ int s[1024];
    int t=threadIdx.x;
    int c = g_cnt[t];
    g_cnt[t] = 0;                      // reset for next replay (module-load value is 0)
    s[t]=c; __syncthreads();
    for(int o=1;o<1024;o<<=1){
        int v = (t>=o)? s[t-o] : 0;
        __syncthreads(); s[t]+=v; __syncthreads();
    }
    int incl = s[t];
    g_off[t] = incl - c;
    g_cur[t] = incl - c;
    if(t==1023) g_off[1024]=incl;
}
__global__ void k_fill(const int* __restrict__ senders){
    int e=blockIdx.x*256+threadIdx.x; if(e>=NE) return;
    int s=senders[e];
    int pos=atomicAdd(&g_cur[s],1);
    g_eidx[pos]=e;
}

// ---------------- w = x@Ww / 8 via MMA (256 thr, 128 edges/block) ----------------
__global__ void __launch_bounds__(256) k_wmma(){
    __shared__ uint32_t sBh[2048], sBl[2048];
    int t=threadIdx.x;
    for(int q=t;q<512;q+=256){
        ((uint4*)sBh)[q]=((const uint4*)g_Wwh)[q];
        ((uint4*)sBl)[q]=((const uint4*)g_Wwl)[q];
    }
    __syncthreads();

    int w=t>>5, lane=t&31, g=lane>>2, tg=lane&3;
    int e0 = blockIdx.x*128 + w*16;

    float acc[8][4];
    #pragma unroll
    for(int i=0;i<8;i++){ acc[i][0]=0.f; acc[i][1]=0.f; acc[i][2]=0.f; acc[i][3]=0.f; }
    const uint2* Ap = (const uint2*)g_hp;
    const uint2* ar0 = Ap + (e0+g  )*128 + tg;
    const uint2* ar1 = Ap + (e0+g+8)*128 + tg;
    #pragma unroll
    for(int kt=0;kt<4;kt++){
        uint2 q0=ar0[kt*8],   q2=ar0[kt*8+4];
        uint2 q1=ar1[kt*8],   q3=ar1[kt*8+4];
        uint32_t a0h=__byte_perm(q0.x,q0.y,0x5410), a0l=__byte_perm(q0.x,q0.y,0x7632);
        uint32_t a1h=__byte_perm(q1.x,q1.y,0x5410), a1l=__byte_perm(q1.x,q1.y,0x7632);
        uint32_t a2h=__byte_perm(q2.x,q2.y,0x5410), a2l=__byte_perm(q2.x,q2.y,0x7632);
        uint32_t a3h=__byte_perm(q3.x,q3.y,0x5410), a3l=__byte_perm(q3.x,q3.y,0x7632);
        #pragma unroll
        for(int nt=0;nt<8;nt++){
            int bi=(nt*8+g)*32 + kt*8 + tg;
            uint32_t b0h=sBh[bi], b1h=sBh[bi+4];
            uint32_t b0l=sBl[bi], b1l=sBl[bi+4];
            mma16816(acc[nt], a0h,a1h,a2h,a3h, b0h,b1h);
            mma16816(acc[nt], a0h,a1h,a2h,a3h, b0l,b1l);
            mma16816(acc[nt], a0l,a1l,a2l,a3l, b0h,b1h);
        }
    }
    int eg0=e0+g, eg1=e0+g+8;
    float* o0 = g_w + eg0*64 + tg*2;
    float* o1 = g_w + eg1*64 + tg*2;
    #pragma unroll
    for(int nt=0;nt<8;nt++){
        *(float2*)(o0 + nt*8) = make_float2(acc[nt][0]*0.125f, acc[nt][1]*0.125f);
        *(float2*)(o1 + nt*8) = make_float2(acc[nt][2]*0.125f, acc[nt][3]*0.125f);
    }
}

// ---------------- atomic-free node aggregation: warp per node ----------------
__global__ void __launch_bounds__(128) k_gather(){
    int t=threadIdx.x, w=t>>5, lane=t&31;
    int b = blockIdx.x*4 + w;
    int beg=g_off[b], end=g_off[b+1];
    float acc0[16], acc1[16];
    #pragma unroll
    for(int k=0;k<16;k++){ acc0[k]=0.f; acc1[k]=0.f; }
    for(int j=beg;j<end;j++){
        int e=g_eidx[j];
        float2 wv = *(const float2*)(g_w + (size_t)e*64 + lane*2);
        const float4* yp = (const float4*)(g_Yt + (size_t)e*16);
        float4 y0=yp[0], y1=yp[1], y2=yp[2], y3=yp[3];
        float Y[16] = {y0.x,y0.y,y0.z,y0.w, y1.x,y1.y,y1.z,y1.w,
                       y2.x,y2.y,y2.z,y2.w, y3.x,y3.y,y3.z,y3.w};
        #pragma unroll
        for(int k=0;k<16;k++){ acc0[k]+=wv.x*Y[k]; acc1[k]+=wv.y*Y[k]; }
    }
    float4* np0 = (float4*)(g_node + ((size_t)b*64 + lane*2)*16);
    np0[0]=make_float4(acc0[0],acc0[1],acc0[2],acc0[3]);
    np0[1]=make_float4(acc0[4],acc0[5],acc0[6],acc0[7]);
    np0[2]=make_float4(acc0[8],acc0[9],acc0[10],acc0[11]);
    np0[3]=make_float4(acc0[12],acc0[13],acc0[14],acc0[15]);
    np0[4]=make_float4(acc1[0],acc1[1],acc1[2],acc1[3]);
    np0[5]=make_float4(acc1[4],acc1[5],acc1[6],acc1[7]);
    np0[6]=make_float4(acc1[8],acc1[9],acc1[10],acc1[11]);
    np0[7]=make_float4(acc1[12],acc1[13],acc1[14],acc1[15]);
}

// ---------------- 13 CG tensor-product paths: parity-sparse, 8 edges/block, 2 ch/thread ----------------
// Parity vectors (bits: x=4,y=2,z=1). CG entry is EXACTLY zero unless parities XOR to 0.
#define PTP_PAR1(i) ((i)==0?4:((i)==1?2:1))
#define PTP_PAR2(j) ((j)==0?6:((j)==1?3:((j)==2?0:((j)==3?5:0))))
#define PTP_PAR3(i) ((i)==0?2:((i)==1?7:((i)==2?2:((i)==3?1:((i)==4?4:((i)==5?1:4))))))
__global__ void k_tp(const float* __restrict__ V, const int* __restrict__ senders){
    __shared__ float cg[573];
    int t=threadIdx.x;
    for(int q=t;q<573;q+=256) cg[q]=g_cg[q];
    __syncthreads();
    int e = blockIdx.x*8 + (t>>5);
    int q2 = t&31;
    int n0 = q2*2;                    // thread owns channels n0, n0+1
    int s = senders[e];
    float A[2][16], B[2][9];
    #pragma unroll
    for(int cc=0;cc<2;cc++){
        const float4* ap4 = (const float4*)(g_node + ((size_t)s*64+n0+cc)*16);
        float4 a0=ap4[0], a1=ap4[1], a2=ap4[2], a3=ap4[3];
        A[cc][0]=a0.x*0.25f; A[cc][1]=a0.y*0.25f; A[cc][2]=a0.z*0.25f; A[cc][3]=a0.w*0.25f;
        A[cc][4]=a1.x*0.25f; A[cc][5]=a1.y*0.25f; A[cc][6]=a1.z*0.25f; A[cc][7]=a1.w*0.25f;
        A[cc][8]=a2.x*0.25f; A[cc][9]=a2.y*0.25f; A[cc][10]=a2.z*0.25f; A[cc][11]=a2.w*0.25f;
        A[cc][12]=a3.x*0.25f; A[cc][13]=a3.y*0.25f; A[cc][14]=a3.z*0.25f; A[cc][15]=a3.w*0.25f;
        const float* bp = V + ((size_t)e*64+n0+cc)*9;
        #pragma unroll
        for(int j=0;j<9;j++) B[cc][j]=bp[j];
    }

    // scalars -> g_hp (k = 64 + n*3 + p)
    {
        float s0[2], s1[2]={0.f,0.f}, s2[2]={0.f,0.f};
        float c0 = cg[0];
        s0[0]=A[0][0]*B[0][0]*c0; s0[1]=A[1][0]*B[1][0]*c0;
        #pragma unroll
        for(int i=0;i<3;i++)
            #pragma unroll
            for(int j=0;j<3;j++) if((PTP_PAR1(i)^PTP_PAR1(j))==0){ float c=cg[1+i*3+j];
                s1[0]+=A[0][1+i]*B[0][1+j]*c; s1[1]+=A[1][1+i]*B[1][1+j]*c; }
        #pragma unroll
        for(int i=0;i<5;i++)
            #pragma unroll
            for(int j=0;j<5;j++) if((PTP_PAR2(i)^PTP_PAR2(j))==0){ float c=cg[10+i*5+j];
                s2[0]+=A[0][4+i]*B[0][4+j]*c; s2[1]+=A[1][4+i]*B[1][4+j]*c; }
        int hb = e*256 + 64 + n0*3;
        g_hp[hb+0]=pack_hl(s0[0]); g_hp[hb+1]=pack_hl(s1[0]); g_hp[hb+2]=pack_hl(s2[0]);
        g_hp[hb+3]=pack_hl(s0[1]); g_hp[hb+4]=pack_hl(s1[1]); g_hp[hb+5]=pack_hl(s2[1]);
    }

    // V1 paths
    {
        float o[5][3][2];
        #pragma unroll
        for(int p=0;p<5;p++)
            #pragma unroll
            for(int i=0;i<3;i++){ o[p][i][0]=0.f; o[p][i][1]=0.f; }
        #pragma unroll
        for(int j=0;j<3;j++){
            float ab0=A[0][0]*B[0][1+j], ab1=A[1][0]*B[1][1+j];
            #pragma unroll
            for(int k=0;k<3;k++) if((PTP_PAR1(j)^PTP_PAR1(k))==0){ float c=cg[35+j*3+k]; o[0][k][0]+=ab0*c; o[0][k][1]+=ab1*c; }
        }
        #pragma unroll
        for(int i=0;i<3;i++){
            float ab0=A[0][1+i]*B[0][0], ab1=A[1][1+i]*B[1][0];
            #pragma unroll
            for(int k=0;k<3;k++) if((PTP_PAR1(i)^PTP_PAR1(k))==0){ float c=cg[44+i*3+k]; o[1][k][0]+=ab0*c; o[1][k][1]+=ab1*c; }
        }
        #pragma unroll
        for(int i=0;i<3;i++)
            #pragma unroll
            for(int j=0;j<5;j++){
                float ab0=A[0][1+i]*B[0][4+j], ab1=A[1][1+i]*B[1][4+j];
                int c0i=53+(i*5+j)*3;
                #pragma unroll
                for(int k=0;k<3;k++) if((PTP_PAR1(i)^PTP_PAR2(j)^PTP_PAR1(k))==0){ float c=cg[c0i+k]; o[2][k][0]+=ab0*c; o[2][k][1]+=ab1*c; }
            }
        #pragma unroll
        for(int i=0;i<5;i++)
            #pragma unroll
            for(int j=0;j<3;j++){
                float ab0=A[0][4+i]*B[0][1+j], ab1=A[1][4+i]*B[1][1+j];
                int c0i=98+(i*3+j)*3;
                #pragma unroll
                for(int k=0;k<3;k++) if((PTP_PAR2(i)^PTP_PAR1(j)^PTP_PAR1(k))==0){ float c=cg[c0i+k]; o[3][k][0]+=ab0*c; o[3][k][1]+=ab1*c; }
            }
        #pragma unroll
        for(int i=0;i<7;i++)
            #pragma unroll
            for(int j=0;j<5;j++){
                float ab0=A[0][9+i]*B[0][4+j], ab1=A[1][9+i]*B[1][4+j];
                int c0i=143+(i*5+j)*3;
                #pragma unroll
                for(int k=0;k<3;k++) if((PTP_PAR3(i)^PTP_PAR2(j)^PTP_PAR1(k))==0){ float c=cg[c0i+k]; o[4][k][0]+=ab0*c; o[4][k][1]+=ab1*c; }
            }
        #pragma unroll
        for(int p=0;p<5;p++)
            #pragma unroll
            for(int i=0;i<3;i++){
                int b = e*960 + i*320 + p*64 + n0;
                uint2 v; v.x=pack_hl(o[p][i][0]); v.y=pack_hl(o[p][i][1]);
                *(uint2*)(g_V1p + b) = v;
            }
    }

    // V2 paths
    {
        float o[5][5][2];
        #pragma unroll
        for(int p=0;p<5;p++)
            #pragma unroll
            for(int k=0;k<5;k++){ o[p][k][0]=0.f; o[p][k][1]=0.f; }
        #pragma unroll
        for(int j=0;j<5;j++){
            float ab0=A[0][0]*B[0][4+j], ab1=A[1][0]*B[1][4+j];
            int c0i=248+j*5;
            #pragma unroll
            for(int k=0;k<5;k++) if((PTP_PAR2(j)^PTP_PAR2(k))==0){ float c=cg[c0i+k]; o[0][k][0]+=ab0*c; o[0][k][1]+=ab1*c; }
        }
        #pragma unroll
        for(int i=0;i<3;i++)
            #pragma unroll
            for(int j=0;j<3;j++){
                float ab0=A[0][1+i]*B[0][1+j], ab1=A[1][1+i]*B[1][1+j];
                int c0i=273+(i*3+j)*5;
                #pragma unroll
                for(int k=0;k<5;k++) if((PTP_PAR1(i)^PTP_PAR1(j)^PTP_PAR2(k))==0){ float c=cg[c0i+k]; o[1][k][0]+=ab0*c; o[1][k][1]+=ab1*c; }
            }
        #pragma unroll
        for(int i=0;i<5;i++){
            float ab0=A[0][4+i]*B[0][0], ab1=A[1][4+i]*B[1][0];
            int c0i=318+i*5;
            #pragma unroll
            for(int k=0;k<5;k++) if((PTP_PAR2(i)^PTP_PAR2(k))==0){ float c=cg[c0i+k]; o[2][k][0]+=ab0*c; o[2][k][1]+=ab1*c; }
        }
        #pragma unroll
        for(int i=0;i<5;i++)
            #pragma unroll
            for(int j=0;j<5;j++){
                float ab0=A[0][4+i]*B[0][4+j], ab1=A[1][4+i]*B[1][4+j];
                int c0i=343+(i*5+j)*5;
                #pragma unroll
                for(int k=0;k<5;k++) if((PTP_PAR2(i)^PTP_PAR2(j)^PTP_PAR2(k))==0){ float c=cg[c0i+k]; o[3][k][0]+=ab0*c; o[3][k][1]+=ab1*c; }
            }
        #pragma unroll
        for(int i=0;i<7;i++)
            #pragma unroll
            for(int j=0;j<3;j++){
                float ab0=A[0][9+i]*B[0][1+j], ab1=A[1][9+i]*B[1][1+j];
                int c0i=468+(i*3+j)*5;
                #pragma unroll
                for(int k=0;k<5;k++) if((PTP_PAR3(i)^PTP_PAR1(j)^PTP_PAR2(k))==0){ float c=cg[c0i+k]; o[4][k][0]+=ab0*c; o[4][k][1]+=ab1*c; }
            }
        #pragma unroll
        for(int p=0;p<5;p++)
            #pragma unroll
            for(int k=0;k<5;k++){
                int b = e*1600 + k*320 + p*64 + n0;
                uint2 v; v.x=pack_hl(o[p][k][0]); v.y=pack_hl(o[p][k][1]);
                *(uint2*)(g_V2p + b) = v;
            }
    }
}

// ---------------- fused GEMM + V_out pack: 32 edges/block (96 V1-rows + 160 V2-rows = 256 M-rows) ----------------
// smem: B planes [h1|l1|h2|l2] 163840 B during MMA; aliased as sC[256][65] floats for epilogue.
#define GP_SMEM 163840
__global__ void __launch_bounds__(256) k_gemmpack(float* __restrict__ vout){
    extern __shared__ uint32_t smg[];
    float* sC = (float*)smg;          // alias, valid after post-MMA barrier
    int t=threadIdx.x;
    for(int q=t;q<2560;q+=256){
        ((uint4*)smg)[q       ] = ((const uint4*)g_WvBh1)[q];
        ((uint4*)smg)[q+2560  ] = ((const uint4*)g_WvBl1)[q];
        ((uint4*)smg)[q+5120  ] = ((const uint4*)g_WvBh2)[q];
        ((uint4*)smg)[q+7680  ] = ((const uint4*)g_WvBl2)[q];
    }
    __syncthreads();

    int w=t>>5, lane=t&31, g=lane>>2, tg=lane&3;
    long e0 = (long)blockIdx.x*32;
    const float sc = 0.05590169943749474f;   // 1/sqrt(320)

    float accs[2][8][4];
    #pragma unroll
    for(int rt=0;rt<2;rt++){
        int m = w*2+rt;                      // m-tile 0..15; m<6 -> V1, else V2
        bool one = (m<6);
        const uint2* Ag = (const uint2*)(one ? g_V1p : g_V2p);
        const uint32_t* bh = (one ? smg         : smg+20480) + g*160 + tg;
        const uint32_t* bl = (one ? smg+10240   : smg+30720) + g*160 + tg;
        long row0 = one ? (e0*3 + (long)m*16) : (e0*5 + (long)(m-6)*16);
        float (*acc)[4] = accs[rt];
        #pragma unroll
        for(int i=0;i<8;i++){ acc[i][0]=0.f; acc[i][1]=0.f; acc[i][2]=0.f; acc[i][3]=0.f; }
        const uint2* arow0 = Ag + (row0+g  )*160 + tg;
        const uint2* arow1 = Ag + (row0+g+8)*160 + tg;

        #pragma unroll 2
        for(int kt=0; kt<20; kt++){
            uint2 q0 = arow0[kt*8];
            uint2 q2 = arow0[kt*8+4];
            uint2 q1 = arow1[kt*8];
            uint2 q3 = arow1[kt*8+4];
            uint32_t a0h=__byte_perm(q0.x,q0.y,0x5410), a0l=__byte_perm(q0.x,q0.y,0x7632);
            uint32_t a1h=__byte_perm(q1.x,q1.y,0x5410), a1l=__byte_perm(q1.x,q1.y,0x7632);
            uint32_t a2h=__byte_perm(q2.x,q2.y,0x5410), a2l=__byte_perm(q2.x,q2.y,0x7632);
            uint32_t a3h=__byte_perm(q3.x,q3.y,0x5410), a3l=__byte_perm(q3.x,q3.y,0x7632);
            #pragma unroll
            for(int nt=0;nt<8;nt++){
                int bi = nt*8*160 + kt*8;
                uint32_t b0h=bh[bi],  b1h=bh[bi+4];
                uint32_t b0l=bl[bi],  b1l=bl[bi+4];
                mma16816(acc[nt], a0h,a1h,a2h,a3h, b0h,b1h);
                mma16816(acc[nt], a0h,a1h,a2h,a3h, b0l,b1l);
                mma16816(acc[nt], a0l,a1l,a2l,a3l, b0h,b1h);
            }
        }
    }
    __syncthreads();    // all B smem reads done; sC may alias

    #pragma unroll
    for(int rt=0;rt<2;rt++){
        int lr = (w*2+rt)*16;
        #pragma unroll
        for(int nt=0;nt<8;nt++){
            int col = nt*8 + tg*2;
            sC[(lr+g  )*65+col]   = accs[rt][nt][0]*sc;
            sC[(lr+g  )*65+col+1] = accs[rt][nt][1]*sc;
            sC[(lr+g+8)*65+col]   = accs[rt][nt][2]*sc;
            sC[(lr+g+8)*65+col+1] = accs[rt][nt][3]*sc;
        }
    }
    __syncthreads();

    // pack 32 edges x 576 directly to V_out (local V1 rows 0..95, V2 rows 96..255)
    for(int idx=t; idx<18432; idx+=256){
        int le = idx/576, r = idx - le*576;
        int o = r/9, c = r - o*9;
        float v = 0.f;
        if(c>=1 && c<4)      v = sC[(le*3 + c-1)*65 + o];
        else if(c>=4)        v = sC[(96 + le*5 + c-4)*65 + o];
        vout[(e0+le)*576 + r] = v;
    }
}

// ---------------- fused 3-layer MMA MLP (256 thr, 128 edges/block) ----------------
__global__ void __launch_bounds__(256) k_mlpmma(float* __restrict__ xout){
    extern __shared__ uint32_t sm[];
    uint32_t* sW1h = sm;
    uint32_t* sW1l = sm + 8192;
    uint32_t* sW2h = sm + 16384;
    uint32_t* sW2l = sm + 18432;
    uint32_t* sW3h = sm + 20480;
    uint32_t* sW3l = sm + 22528;
    int t=threadIdx.x;
    for(int q=t;q<2048;q+=256){ ((uint4*)sW1h)[q]=((const uint4*)g_W1h)[q]; ((uint4*)sW1l)[q]=((const uint4*)g_W1l)[q]; }
    for(int q=t;q<512;q+=256){
        ((uint4*)sW2h)[q]=((const uint4*)g_W2h)[q]; ((uint4*)sW2l)[q]=((const uint4*)g_W2l)[q];
        ((uint4*)sW3h)[q]=((const uint4*)g_W3h)[q]; ((uint4*)sW3l)[q]=((const uint4*)g_W3l)[q];
    }
    __syncthreads();

    int w=t>>5, lane=t&31, g=lane>>2, tg=lane&3;
    int e0 = blockIdx.x*128 + w*16;
    float inv_actc = 1.0f/g_actc;

    float acc[8][4];
    #pragma unroll
    for(int i=0;i<8;i++){ acc[i][0]=0.f; acc[i][1]=0.f; acc[i][2]=0.f; acc[i][3]=0.f; }
    const uint2* Ap = (const uint2*)g_hp;
    const uint2* ar0 = Ap + (e0+g  )*128 + tg;
    const uint2* ar1 = Ap + (e0+g+8)*128 + tg;
    #pragma unroll 2
    for(int kt=0;kt<16;kt++){
        uint2 q0=ar0[kt*8],   q2=ar0[kt*8+4];
        uint2 q1=ar1[kt*8],   q3=ar1[kt*8+4];
        uint32_t a0h=__byte_perm(q0.x,q0.y,0x5410), a0l=__byte_perm(q0.x,q0.y,0x7632);
        uint32_t a1h=__byte_perm(q1.x,q1.y,0x5410), a1l=__byte_perm(q1.x,q1.y,0x7632);
        uint32_t a2h=__byte_perm(q2.x,q2.y,0x5410), a2l=__byte_perm(q2.x,q2.y,0x7632);
        uint32_t a3h=__byte_perm(q3.x,q3.y,0x5410), a3l=__byte_perm(q3.x,q3.y,0x7632);
        #pragma unroll
        for(int nt=0;nt<8;nt++){
            int bi=(nt*8+g)*128 + kt*8 + tg;
            uint32_t b0h=sW1h[bi], b1h=sW1h[bi+4];
            uint32_t b0l=sW1l[bi], b1l=sW1l[bi+4];
            mma16816(acc[nt], a0h,a1h,a2h,a3h, b0h,b1h);
            mma16816(acc[nt], a0h,a1h,a2h,a3h, b0l,b1l);
            mma16816(acc[nt], a0l,a1l,a2l,a3l, b0h,b1h);
        }
    }
    float v[8][4];
    #pragma unroll
    for(int nt=0;nt<8;nt++)
        #pragma unroll
        for(int j=0;j<4;j++){
            float a = acc[nt][j]*0.0625f;
            v[nt][j] = a*__fdividef(1.f, 1.f+__expf(-a))*inv_actc;
        }

    #pragma unroll
    for(int i=0;i<8;i++){ acc[i][0]=0.f; acc[i][1]=0.f; acc[i][2]=0.f; acc[i][3]=0.f; }
    #pragma unroll
    for(int kt=0;kt<4;kt++){
        uint32_t a0h,a0l,a1h,a1l,a2h,a2l,a3h,a3l;
        split2(v[2*kt][0],  v[2*kt][1],   a0h,a0l);
        split2(v[2*kt][2],  v[2*kt][3],   a1h,a1l);
        split2(v[2*kt+1][0],v[2*kt+1][1], a2h,a2l);
        split2(v[2*kt+1][2],v[2*kt+1][3], a3h,a3l);
        #pragma unroll
        for(int nt=0;nt<8;nt++){
            int bi=(nt*8+g)*32 + kt*8 + tg;
            uint32_t b0h=sW2h[bi], b1h=sW2h[bi+4];
            uint32_t b0l=sW2l[bi], b1l=sW2l[bi+4];
            mma16816(acc[nt], a0h,a1h,a2h,a3h, b0h,b1h);
            mma16816(acc[nt], a0h,a1h,a2h,a3h, b0l,b1l);
            mma16816(acc[nt], a0l,a1l,a2l,a3l, b0h,b1h);
        }
    }
    #pragma unroll
    for(int nt=0;nt<8;nt++)
        #pragma unroll
        for(int j=0;j<4;j++){
            float a = acc[nt][j]*0.125f;
            v[nt][j] = a*__fdividef(1.f, 1.f+__expf(-a))*inv_actc;
        }

    #pragma unroll
    for(int i=0;i<8;i++){ acc[i][0]=0.f; acc[i][1]=0.f; acc[i][2]=0.f; acc[i][3]=0.f; }
    #pragma unroll
    for(int kt=0;kt<4;kt++){
        uint32_t a0h,a0l,a1h,a1l,a2h,a2l,a3h,a3l;
        split2(v[2*kt][0],  v[2*kt][1],   a0h,a0l);
        split2(v[2*kt][2],  v[2*kt][3],   a1h,a1l);
        split2(v[2*kt+1][0],v[2*kt+1][1], a2h,a2l);
        split2(v[2*kt+1][2],v[2*kt+1][3], a3h,a3l);
        #pragma unroll
        for(int nt=0;nt<8;nt++){
            int bi=(nt*8+g)*32 + kt*8 + tg;
            uint32_t b0h=sW3h[bi], b1h=sW3h[bi+4];
            uint32_t b0l=sW3l[bi], b1l=sW3l[bi+4];
            mma16816(acc[nt], a0h,a1h,a2h,a3h, b0h,b1h);
            mma16816(acc[nt], a0h,a1h,a2h,a3h, b0l,b1l);
            mma16816(acc[nt], a0l,a1l,a2l,a3l, b0h,b1h);
        }
    }

    int eg0=e0+g, eg1=e0+g+8;
    float d0=g_d[eg0], d1=g_d[eg1];
    float f0=0.f, f1=0.f;
    if(d0<1.f){ float d3=d0*d0*d0, d6=d3*d3, d7=d6*d0, d8=d7*d0; f0=(1.f-28.f*d6+48.f*d7-21.f*d8)*0.125f; }
    if(d1<1.f){ float d3=d1*d1*d1, d6=d3*d3, d7=d6*d1, d8=d7*d1; f1=(1.f-28.f*d6+48.f*d7-21.f*d8)*0.125f; }
    float* o0 = xout + eg0*64 + tg*2;
    float* o1 = xout + eg1*64 + tg*2;
    #pragma unroll
    for(int nt=0;nt<8;nt++){
        *(float2*)(o0 + nt*8) = make_float2(acc[nt][0]*f0, acc[nt][1]*f0);
        *(float2*)(o1 + nt*8) = make_float2(acc[nt][2]*f1, acc[nt][3]*f1);
    }
}

// ---------------- launch ----------------
extern "C" void kernel_launch(void* const* d_in, const int* in_sizes, int n_in,
                              void* d_out, int out_size){
    const float* vectors = (const float*)d_in[0];
    const float* x       = (const float*)d_in[1];
    const float* V       = (const float*)d_in[2];
    const int*   senders = (const int*)  d_in[3];
    const float* Ww      = (const float*)d_in[4];
    const float* W1      = (const float*)d_in[5];
    const float* W2      = (const float*)d_in[6];
    const float* W3      = (const float*)d_in[7];
    const float* Wv1     = (const float*)d_in[8];
    const float* Wv2     = (const float*)d_in[9];
    float* out  = (float*)d_out;
    float* vout = out + (size_t)NE*64;

    host_compute_constants();
    cudaMemcpyToSymbolAsync(g_cg,   s_cg_host,    sizeof(s_cg_host), 0, cudaMemcpyHostToDevice, 0);
    cudaMemcpyToSymbolAsync(g_actc, &s_actc_host, sizeof(float),     0, cudaMemcpyHostToDevice, 0);

    const int SMEM_MLP = 24576*4;   // 98304 B
    cudaFuncSetAttribute(k_gemmpack, cudaFuncAttributeMaxDynamicSharedMemorySize, GP_SMEM);
    cudaFuncSetAttribute(k_mlpmma,   cudaFuncAttributeMaxDynamicSharedMemorySize, SMEM_MLP);

    k_prep<<<PREP_WPACK_BLOCKS + NE/4,256>>>(Wv1, Wv2, W1, W2, W3, Ww, x, vectors, senders);
    k_wmma<<<NE/128,256>>>();
    k_scan<<<1,1024>>>();
    k_fill<<<64,256>>>(senders);
    k_gather<<<NNODES/4,128>>>();
    k_tp<<<NE/8,256>>>(V, senders);
    k_gemmpack<<<NE/32,256,GP_SMEM>>>(vout);
    k_mlpmma<<<NE/128,256,SMEM_MLP>>>(out);
}

// round 16
// speedup vs baseline: 1.7765x; 1.7765x over previous
#include <cuda_runtime.h>
#include <cuda_bf16.h>
#include <math.h>
#include <stdint.h>

#define NE 16384
#define NNODES 1024
#define PI_D 3.14159265358979323846

// ---------------- scratch ----------------
__device__ float    g_cg[573];
__device__ float    g_actc;
__device__ float    g_node[NNODES * 64 * 16];
__device__ float    g_d[NE];
__device__ float    g_w[NE * 64];
__device__ float    g_Yt[NE * 16];
__device__ __align__(16) uint32_t g_hp[NE * 256];       // packed MLP input [e][k]
__device__ __align__(16) uint32_t g_V1p[NE * 3 * 320];  // packed (hi bf16 | lo bf16<<16), row=(e*3+i), K=320
__device__ __align__(16) uint32_t g_V2p[NE * 5 * 320];  // row=(e*5+k)
__device__ __align__(16) uint32_t g_WvBh1[64 * 160];
__device__ __align__(16) uint32_t g_WvBl1[64 * 160];
__device__ __align__(16) uint32_t g_WvBh2[64 * 160];
__device__ __align__(16) uint32_t g_WvBl2[64 * 160];
__device__ __align__(16) uint32_t g_W1h[64 * 128];
__device__ __align__(16) uint32_t g_W1l[64 * 128];
__device__ __align__(16) uint32_t g_W2h[64 * 32];
__device__ __align__(16) uint32_t g_W2l[64 * 32];
__device__ __align__(16) uint32_t g_W3h[64 * 32];
__device__ __align__(16) uint32_t g_W3l[64 * 32];
__device__ __align__(16) uint32_t g_Wwh[64 * 32];
__device__ __align__(16) uint32_t g_Wwl[64 * 32];
__device__ float    g_C1[NE * 3 * 64];
__device__ float    g_C2[NE * 5 * 64];
__device__ int      g_cnt[NNODES];      // zero-init at load; k_scan re-zeroes after read
__device__ int      g_off[NNODES + 1];
__device__ int      g_cur[NNODES];
__device__ int      g_eidx[NE];

// ---------------- device helpers ----------------
__device__ __forceinline__ uint32_t pack_hl(float v){
    __nv_bfloat16 h = __float2bfloat16(v);
    float hf = __bfloat162float(h);
    __nv_bfloat16 l = __float2bfloat16(v - hf);
    return (uint32_t)__bfloat16_as_ushort(h) | ((uint32_t)__bfloat16_as_ushort(l) << 16);
}
__device__ __forceinline__ void split2(float v0, float v1, uint32_t& h, uint32_t& l){
    uint32_t p0 = pack_hl(v0), p1 = pack_hl(v1);
    h = __byte_perm(p0, p1, 0x5410);
    l = __byte_perm(p0, p1, 0x7632);
}
__device__ __forceinline__ void mma16816(float* d,
        uint32_t a0, uint32_t a1, uint32_t a2, uint32_t a3,
        uint32_t b0, uint32_t b1){
    asm volatile(
        "mma.sync.aligned.m16n8k16.row.col.f32.bf16.bf16.f32 "
        "{%0,%1,%2,%3}, {%4,%5,%6,%7}, {%8,%9}, {%0,%1,%2,%3};"
        : "+f"(d[0]), "+f"(d[1]), "+f"(d[2]), "+f"(d[3])
        : "r"(a0), "r"(a1), "r"(a2), "r"(a3), "r"(b0), "r"(b1));
}

// ---------------- host-side CG + ACT_C ----------------
static const int h_l1[13]  = {0,1,2, 0,1,1,2,3, 0,1,2,2,3};
static const int h_l2[13]  = {0,1,2, 1,0,2,1,2, 2,1,0,2,1};
static const int h_l3[13]  = {0,0,0, 1,1,1,1,1, 2,2,2,2,2};
static const int h_offs[14]= {0,1,10,35,44,53,98,143,248,273,318,343,468,573};

static double h_dfact(int n){ double r=1.0; while(n>1){ r*=(double)n; n-=2; } return r; }
static double h_mono(int a,int b,int c){
    if((a&1)||(b&1)||(c&1)) return 0.0;
    return 4.0*PI_D*h_dfact(a-1)*h_dfact(b-1)*h_dfact(c-1)/h_dfact(a+b+c+1);
}
static int h_sh(int l,int m,double* c,int (*ex)[3]){
    double S3=sqrt(3.0), S5=sqrt(5.0), S15=sqrt(15.0);
    double C33=sqrt(70.0)/4.0, C32=sqrt(105.0)/2.0, C31=sqrt(42.0)/4.0, C30=sqrt(7.0)/2.0, CX=sqrt(105.0);
#define TT(t,cc,a,b,cz) { c[t]=(cc); ex[t][0]=(a); ex[t][1]=(b); ex[t][2]=(cz); }
    if(l==0){ TT(0,1.0,0,0,0); return 1; }
    if(l==1){
        if(m==0){ TT(0,S3,1,0,0); } else if(m==1){ TT(0,S3,0,1,0); } else { TT(0,S3,0,0,1); }
        return 1;
    }
    if(l==2){
        switch(m){
            case 0: TT(0,S15,1,1,0); return 1;
            case 1: TT(0,S15,0,1,1); return 1;
            case 2: TT(0,1.5*S5,0,0,2); TT(1,-0.5*S5,0,0,0); return 2;
            case 3: TT(0,S15,1,0,1); return 1;
            default: TT(0,0.5*S15,2,0,0); TT(1,-0.5*S15,0,2,0); return 2;
        }
    }
    switch(m){
        case 0: TT(0,3.0*C33,2,1,0); TT(1,-C33,0,3,0); return 2;
        case 1: TT(0,CX,1,1,1); return 1;
        case 2: TT(0,5.0*C31,0,1,2); TT(1,-C31,0,1,0); return 2;
        case 3: TT(0,5.0*C30,0,0,3); TT(1,-3.0*C30,0,0,1); return 2;
        case 4: TT(0,5.0*C31,1,0,2); TT(1,-C31,1,0,0); return 2;
        case 5: TT(0,C32,2,0,1); TT(1,-C32,0,2,1); return 2;
        default: TT(0,C33,3,0,0); TT(1,-3.0*C33,1,2,0); return 2;
    }
#undef TT
}

static float s_cg_host[573];
static float s_actc_host;

static void host_compute_constants(){
    double raw[573];
    for(int p=0;p<13;p++){
        int l1=h_l1[p], l2=h_l2[p], l3=h_l3[p];
        int n1=2*l1+1, n2=2*l2+1, n3=2*l3+1;
        int off=h_offs[p];
        for(int i=0;i<n1;i++) for(int j=0;j<n2;j++) for(int k=0;k<n3;k++){
            double c1[2],c2[2],c3[2]; int e1[2][3],e2[2][3],e3[2][3];
            int t1=h_sh(l1,i,c1,e1), t2=h_sh(l2,j,c2,e2), t3=h_sh(l3,k,c3,e3);
            double v=0.0;
            for(int a=0;a<t1;a++) for(int b=0;b<t2;b++) for(int cc=0;cc<t3;cc++)
                v += c1[a]*c2[b]*c3[cc]*h_mono(e1[a][0]+e2[b][0]+e3[cc][0],
                                              e1[a][1]+e2[b][1]+e3[cc][1],
                                              e1[a][2]+e2[b][2]+e3[cc][2]);
            raw[off + (i*n2+j)*n3 + k] = v/(4.0*PI_D);
        }
        double s=0.0;
        for(int q=off;q<h_offs[p+1];q++) s += raw[q]*raw[q];
        double sc = sqrt((double)(2*l3+1))/sqrt(s);
        for(int q=off;q<h_offs[p+1];q++) s_cg_host[q] = (float)(raw[q]*sc);
    }
    double step = 24.0/200000.0, acc=0.0;
    for(int i=0;i<=200000;i++){
        double z = -12.0 + step*(double)i;
        double phi = exp(-0.5*z*z)*0.39894228040143267794;
        double sl = z/(1.0+exp(-z));
        acc += sl*sl*phi;
    }
    s_actc_host = (float)sqrt(acc*step);
}

// ---------------- merged prep: weight packing (blocks < 136) + per-edge (blocks >= 136) ----------------
#define PREP_WPACK_BLOCKS 136
__global__ void k_prep(const float* __restrict__ Wv1, const float* __restrict__ Wv2,
                       const float* __restrict__ W1,  const float* __restrict__ W2,
                       const float* __restrict__ W3,  const float* __restrict__ Ww,
                       const float* __restrict__ x,   const float* __restrict__ vec,
                       const int* __restrict__ senders){
    if(blockIdx.x < PREP_WPACK_BLOCKS){
        int i = blockIdx.x*256+threadIdx.x;
        const float* W; uint32_t *Bh, *Bl; int j, np;
        if(i < 10240){ W=Wv1; Bh=g_WvBh1; Bl=g_WvBl1; j=i; np=160; }
        else if(i < 20480){ W=Wv2; Bh=g_WvBh2; Bl=g_WvBl2; j=i-10240; np=160; }
        else if(i < 28672){ W=W1; Bh=g_W1h; Bl=g_W1l; j=i-20480; np=128; }
        else if(i < 30720){ W=W2; Bh=g_W2h; Bl=g_W2l; j=i-28672; np=32; }
        else if(i < 32768){ W=W3; Bh=g_W3h; Bl=g_W3l; j=i-30720; np=32; }
        else if(i < 34816){ W=Ww; Bh=g_Wwh; Bl=g_Wwl; j=i-32768; np=32; }
        else return;
        int n=j/np, p=j-n*np;
        uint32_t p0 = pack_hl(W[(2*p  )*64 + n]);
        uint32_t p1 = pack_hl(W[(2*p+1)*64 + n]);
        Bh[j] = __byte_perm(p0, p1, 0x5410);
        Bl[j] = __byte_perm(p0, p1, 0x7632);
        return;
    }
    int i = (blockIdx.x - PREP_WPACK_BLOCKS)*256 + threadIdx.x;   // over NE*64
    int e = i>>6, k = i&63;
    g_hp[e*256+k] = pack_hl(x[i]);
    if(k==0){
        atomicAdd(&g_cnt[senders[e]],1);
        float vx=vec[e*3+0], vy=vec[e*3+1], vz=vec[e*3+2];
        float d = sqrtf(vx*vx+vy*vy+vz*vz);
        g_d[e]=d;
        float X=vx/d, Y=vy/d, Z=vz/d;
        const float S3=1.7320508075688772f, S5=2.2360679774997896f, S15=3.8729833462074170f;
        const float C33=2.0916500663351889f, C32=5.1234753829797990f, C31=1.6201851746019651f;
        const float C30=1.3228756555322954f, CX=10.246950765959598f;
        float y[16];
        y[0]=1.f; y[1]=S3*X; y[2]=S3*Y; y[3]=S3*Z;
        y[4]=S15*X*Y; y[5]=S15*Y*Z; y[6]=0.5f*S5*(3.f*Z*Z-1.f); y[7]=S15*X*Z; y[8]=0.5f*S15*(X*X-Y*Y);
        y[9]=C33*Y*(3.f*X*X-Y*Y); y[10]=CX*X*Y*Z; y[11]=C31*Y*(5.f*Z*Z-1.f);
        y[12]=C30*Z*(5.f*Z*Z-3.f); y[13]=C31*X*(5.f*Z*Z-1.f); y[14]=C32*Z*(X*X-Y*Y); y[15]=C33*X*(X*X-3.f*Y*Y);
        float4* yp=(float4*)(g_Yt+e*16);
        yp[0]=make_float4(y[0],y[1],y[2],y[3]);
        yp[1]=make_float4(y[4],y[5],y[6],y[7]);
        yp[2]=make_float4(y[8],y[9],y[10],y[11]);
        yp[3]=make_float4(y[12],y[13],y[14],y[15]);
    }
}

// ---------------- CSR scan (+ self-reset of g_cnt) and fill ----------------
__global__ void k_scan(){
    __shared__ int s[1024];
    int t=threadIdx.x;
    int c = g_cnt[t];
    g_cnt[t] = 0;                      // reset for next replay (module-load value is 0)
    s[t]=c; __syncthreads();
    for(int o=1;o<1024;o<<=1){
        int v = (t>=o)? s[t-o] : 0;
        __syncthreads(); s[t]+=v; __syncthreads();
    }
    int incl = s[t];
    g_off[t] = incl - c;
    g_cur[t] = incl - c;
    if(t==1023) g_off[1024]=incl;
}
__global__ void k_fill(const int* __restrict__ senders){
    int e=blockIdx.x*256+threadIdx.x; if(e>=NE) return;
    int s=senders[e];
    int pos=atomicAdd(&g_cur[s],1);
    g_eidx[pos]=e;
}

// ---------------- w = x@Ww / 8 via MMA (256 thr, 128 edges/block; pad-36 B rows) ----------------
__global__ void __launch_bounds__(256) k_wmma(){
    __shared__ uint32_t sBh[64*36], sBl[64*36];
    int t=threadIdx.x;
    for(int q=t;q<512;q+=256){
        uint4 vh=((const uint4*)g_Wwh)[q], vl=((const uint4*)g_Wwl)[q];
        int w0=q*4, n=w0>>5, p=w0&31, base=n*36+p;
        sBh[base]=vh.x; sBh[base+1]=vh.y; sBh[base+2]=vh.z; sBh[base+3]=vh.w;
        sBl[base]=vl.x; sBl[base+1]=vl.y; sBl[base+2]=vl.z; sBl[base+3]=vl.w;
    }
    __syncthreads();

    int w=t>>5, lane=t&31, g=lane>>2, tg=lane&3;
    int e0 = blockIdx.x*128 + w*16;

    float acc[8][4];
    #pragma unroll
    for(int i=0;i<8;i++){ acc[i][0]=0.f; acc[i][1]=0.f; acc[i][2]=0.f; acc[i][3]=0.f; }
    const uint2* Ap = (const uint2*)g_hp;
    const uint2* ar0 = Ap + (e0+g  )*128 + tg;
    const uint2* ar1 = Ap + (e0+g+8)*128 + tg;
    #pragma unroll
    for(int kt=0;kt<4;kt++){
        uint2 q0=ar0[kt*8],   q2=ar0[kt*8+4];
        uint2 q1=ar1[kt*8],   q3=ar1[kt*8+4];
        uint32_t a0h=__byte_perm(q0.x,q0.y,0x5410), a0l=__byte_perm(q0.x,q0.y,0x7632);
        uint32_t a1h=__byte_perm(q1.x,q1.y,0x5410), a1l=__byte_perm(q1.x,q1.y,0x7632);
        uint32_t a2h=__byte_perm(q2.x,q2.y,0x5410), a2l=__byte_perm(q2.x,q2.y,0x7632);
        uint32_t a3h=__byte_perm(q3.x,q3.y,0x5410), a3l=__byte_perm(q3.x,q3.y,0x7632);
        #pragma unroll
        for(int nt=0;nt<8;nt++){
            int bi=(nt*8+g)*36 + kt*8 + tg;
            uint32_t b0h=sBh[bi], b1h=sBh[bi+4];
            uint32_t b0l=sBl[bi], b1l=sBl[bi+4];
            mma16816(acc[nt], a0h,a1h,a2h,a3h, b0h,b1h);
            mma16816(acc[nt], a0h,a1h,a2h,a3h, b0l,b1l);
            mma16816(acc[nt], a0l,a1l,a2l,a3l, b0h,b1h);
        }
    }
    int eg0=e0+g, eg1=e0+g+8;
    float* o0 = g_w + eg0*64 + tg*2;
    float* o1 = g_w + eg1*64 + tg*2;
    #pragma unroll
    for(int nt=0;nt<8;nt++){
        *(float2*)(o0 + nt*8) = make_float2(acc[nt][0]*0.125f, acc[nt][1]*0.125f);
        *(float2*)(o1 + nt*8) = make_float2(acc[nt][2]*0.125f, acc[nt][3]*0.125f);
    }
}

// ---------------- atomic-free node aggregation: warp per node ----------------
__global__ void __launch_bounds__(128) k_gather(){
    int t=threadIdx.x, w=t>>5, lane=t&31;
    int b = blockIdx.x*4 + w;
    int beg=g_off[b], end=g_off[b+1];
    float acc0[16], acc1[16];
    #pragma unroll
    for(int k=0;k<16;k++){ acc0[k]=0.f; acc1[k]=0.f; }
    for(int j=beg;j<end;j++){
        int e=g_eidx[j];
        float2 wv = *(const float2*)(g_w + (size_t)e*64 + lane*2);
        const float4* yp = (const float4*)(g_Yt + (size_t)e*16);
        float4 y0=yp[0], y1=yp[1], y2=yp[2], y3=yp[3];
        float Y[16] = {y0.x,y0.y,y0.z,y0.w, y1.x,y1.y,y1.z,y1.w,
                       y2.x,y2.y,y2.z,y2.w, y3.x,y3.y,y3.z,y3.w};
        #pragma unroll
        for(int k=0;k<16;k++){ acc0[k]+=wv.x*Y[k]; acc1[k]+=wv.y*Y[k]; }
    }
    float4* np0 = (float4*)(g_node + ((size_t)b*64 + lane*2)*16);
    np0[0]=make_float4(acc0[0],acc0[1],acc0[2],acc0[3]);
    np0[1]=make_float4(acc0[4],acc0[5],acc0[6],acc0[7]);
    np0[2]=make_float4(acc0[8],acc0[9],acc0[10],acc0[11]);
    np0[3]=make_float4(acc0[12],acc0[13],acc0[14],acc0[15]);
    np0[4]=make_float4(acc1[0],acc1[1],acc1[2],acc1[3]);
    np0[5]=make_float4(acc1[4],acc1[5],acc1[6],acc1[7]);
    np0[6]=make_float4(acc1[8],acc1[9],acc1[10],acc1[11]);
    np0[7]=make_float4(acc1[12],acc1[13],acc1[14],acc1[15]);
}

// ---------------- 13 CG tensor-product paths: parity-sparse, 8 edges/block, 2 ch/thread ----------------
#define PTP_PAR1(i) ((i)==0?4:((i)==1?2:1))
#define PTP_PAR2(j) ((j)==0?6:((j)==1?3:((j)==2?0:((j)==3?5:0))))
#define PTP_PAR3(i) ((i)==0?2:((i)==1?7:((i)==2?2:((i)==3?1:((i)==4?4:((i)==5?1:4))))))
__global__ void k_tp(const float* __restrict__ V, const int* __restrict__ senders){
    __shared__ float cg[573];
    int t=threadIdx.x;
    for(int q=t;q<573;q+=256) cg[q]=g_cg[q];
    __syncthreads();
    int e = blockIdx.x*8 + (t>>5);
    int q2 = t&31;
    int n0 = q2*2;
    int s = senders[e];
    float A[2][16], B[2][9];
    #pragma unroll
    for(int cc=0;cc<2;cc++){
        const float4* ap4 = (const float4*)(g_node + ((size_t)s*64+n0+cc)*16);
        float4 a0=ap4[0], a1=ap4[1], a2=ap4[2], a3=ap4[3];
        A[cc][0]=a0.x*0.25f; A[cc][1]=a0.y*0.25f; A[cc][2]=a0.z*0.25f; A[cc][3]=a0.w*0.25f;
        A[cc][4]=a1.x*0.25f; A[cc][5]=a1.y*0.25f; A[cc][6]=a1.z*0.25f; A[cc][7]=a1.w*0.25f;
        A[cc][8]=a2.x*0.25f; A[cc][9]=a2.y*0.25f; A[cc][10]=a2.z*0.25f; A[cc][11]=a2.w*0.25f;
        A[cc][12]=a3.x*0.25f; A[cc][13]=a3.y*0.25f; A[cc][14]=a3.z*0.25f; A[cc][15]=a3.w*0.25f;
        const float* bp = V + ((size_t)e*64+n0+cc)*9;
        #pragma unroll
        for(int j=0;j<9;j++) B[cc][j]=bp[j];
    }

    {
        float s0[2], s1[2]={0.f,0.f}, s2[2]={0.f,0.f};
        float c0 = cg[0];
        s0[0]=A[0][0]*B[0][0]*c0; s0[1]=A[1][0]*B[1][0]*c0;
        #pragma unroll
        for(int i=0;i<3;i++)
            #pragma unroll
            for(int j=0;j<3;j++) if((PTP_PAR1(i)^PTP_PAR1(j))==0){ float c=cg[1+i*3+j];
                s1[0]+=A[0][1+i]*B[0][1+j]*c; s1[1]+=A[1][1+i]*B[1][1+j]*c; }
        #pragma unroll
        for(int i=0;i<5;i++)
            #pragma unroll
            for(int j=0;j<5;j++) if((PTP_PAR2(i)^PTP_PAR2(j))==0){ float c=cg[10+i*5+j];
                s2[0]+=A[0][4+i]*B[0][4+j]*c; s2[1]+=A[1][4+i]*B[1][4+j]*c; }
        int hb = e*256 + 64 + n0*3;
        g_hp[hb+0]=pack_hl(s0[0]); g_hp[hb+1]=pack_hl(s1[0]); g_hp[hb+2]=pack_hl(s2[0]);
        g_hp[hb+3]=pack_hl(s0[1]); g_hp[hb+4]=pack_hl(s1[1]); g_hp[hb+5]=pack_hl(s2[1]);
    }

    {
        float o[5][3][2];
        #pragma unroll
        for(int p=0;p<5;p++)
            #pragma unroll
            for(int i=0;i<3;i++){ o[p][i][0]=0.f; o[p][i][1]=0.f; }
        #pragma unroll
        for(int j=0;j<3;j++){
            float ab0=A[0][0]*B[0][1+j], ab1=A[1][0]*B[1][1+j];
            #pragma unroll
            for(int k=0;k<3;k++) if((PTP_PAR1(j)^PTP_PAR1(k))==0){ float c=cg[35+j*3+k]; o[0][k][0]+=ab0*c; o[0][k][1]+=ab1*c; }
        }
        #pragma unroll
        for(int i=0;i<3;i++){
            float ab0=A[0][1+i]*B[0][0], ab1=A[1][1+i]*B[1][0];
            #pragma unroll
            for(int k=0;k<3;k++) if((PTP_PAR1(i)^PTP_PAR1(k))==0){ float c=cg[44+i*3+k]; o[1][k][0]+=ab0*c; o[1][k][1]+=ab1*c; }
        }
        #pragma unroll
        for(int i=0;i<3;i++)
            #pragma unroll
            for(int j=0;j<5;j++){
                float ab0=A[0][1+i]*B[0][4+j], ab1=A[1][1+i]*B[1][4+j];
                int c0i=53+(i*5+j)*3;
                #pragma unroll
                for(int k=0;k<3;k++) if((PTP_PAR1(i)^PTP_PAR2(j)^PTP_PAR1(k))==0){ float c=cg[c0i+k]; o[2][k][0]+=ab0*c; o[2][k][1]+=ab1*c; }
            }
        #pragma unroll
        for(int i=0;i<5;i++)
            #pragma unroll
            for(int j=0;j<3;j++){
                float ab0=A[0][4+i]*B[0][1+j], ab1=A[1][4+i]*B[1][1+j];
                int c0i=98+(i*3+j)*3;
                #pragma unroll
                for(int k=0;k<3;k++) if((PTP_PAR2(i)^PTP_PAR1(j)^PTP_PAR1(k))==0){ float c=cg[c0i+k]; o[3][k][0]+=ab0*c; o[3][k][1]+=ab1*c; }
            }
        #pragma unroll
        for(int i=0;i<7;i++)
            #pragma unroll
            for(int j=0;j<5;j++){
                float ab0=A[0][9+i]*B[0][4+j], ab1=A[1][9+i]*B[1][4+j];
                int c0i=143+(i*5+j)*3;
                #pragma unroll
                for(int k=0;k<3;k++) if((PTP_PAR3(i)^PTP_PAR2(j)^PTP_PAR1(k))==0){ float c=cg[c0i+k]; o[4][k][0]+=ab0*c; o[4][k][1]+=ab1*c; }
            }
        #pragma unroll
        for(int p=0;p<5;p++)
            #pragma unroll
            for(int i=0;i<3;i++){
                int b = e*960 + i*320 + p*64 + n0;
                uint2 v; v.x=pack_hl(o[p][i][0]); v.y=pack_hl(o[p][i][1]);
                *(uint2*)(g_V1p + b) = v;
            }
    }

    {
        float o[5][5][2];
        #pragma unroll
        for(int p=0;p<5;p++)
            #pragma unroll
            for(int k=0;k<5;k++){ o[p][k][0]=0.f; o[p][k][1]=0.f; }
        #pragma unroll
        for(int j=0;j<5;j++){
            float ab0=A[0][0]*B[0][4+j], ab1=A[1][0]*B[1][4+j];
            int c0i=248+j*5;
            #pragma unroll
            for(int k=0;k<5;k++) if((PTP_PAR2(j)^PTP_PAR2(k))==0){ float c=cg[c0i+k]; o[0][k][0]+=ab0*c; o[0][k][1]+=ab1*c; }
        }
        #pragma unroll
        for(int i=0;i<3;i++)
            #pragma unroll
            for(int j=0;j<3;j++){
                float ab0=A[0][1+i]*B[0][1+j], ab1=A[1][1+i]*B[1][1+j];
                int c0i=273+(i*3+j)*5;
                #pragma unroll
                for(int k=0;k<5;k++) if((PTP_PAR1(i)^PTP_PAR1(j)^PTP_PAR2(k))==0){ float c=cg[c0i+k]; o[1][k][0]+=ab0*c; o[1][k][1]+=ab1*c; }
            }
        #pragma unroll
        for(int i=0;i<5;i++){
            float ab0=A[0][4+i]*B[0][0], ab1=A[1][4+i]*B[1][0];
            int c0i=318+i*5;
            #pragma unroll
            for(int k=0;k<5;k++) if((PTP_PAR2(i)^PTP_PAR2(k))==0){ float c=cg[c0i+k]; o[2][k][0]+=ab0*c; o[2][k][1]+=ab1*c; }
        }
        #pragma unroll
        for(int i=0;i<5;i++)
            #pragma unroll
            for(int j=0;j<5;j++){
                float ab0=A[0][4+i]*B[0][4+j], ab1=A[1][4+i]*B[1][4+j];
                int c0i=343+(i*5+j)*5;
                #pragma unroll
                for(int k=0;k<5;k++) if((PTP_PAR2(i)^PTP_PAR2(j)^PTP_PAR2(k))==0){ float c=cg[c0i+k]; o[3][k][0]+=ab0*c; o[3][k][1]+=ab1*c; }
            }
        #pragma unroll
        for(int i=0;i<7;i++)
            #pragma unroll
            for(int j=0;j<3;j++){
                float ab0=A[0][9+i]*B[0][1+j], ab1=A[1][9+i]*B[1][1+j];
                int c0i=468+(i*3+j)*5;
                #pragma unroll
                for(int k=0;k<5;k++) if((PTP_PAR3(i)^PTP_PAR1(j)^PTP_PAR2(k))==0){ float c=cg[c0i+k]; o[4][k][0]+=ab0*c; o[4][k][1]+=ab1*c; }
            }
        #pragma unroll
        for(int p=0;p<5;p++)
            #pragma unroll
            for(int k=0;k<5;k++){
                int b = e*1600 + k*320 + p*64 + n0;
                uint2 v; v.x=pack_hl(o[p][k][0]); v.y=pack_hl(o[p][k][1]);
                *(uint2*)(g_V2p + b) = v;
            }
    }
}

// ---------------- merged bf16-split GEMM (both o1 and o2; pad-164 B rows) ----------------
#define NB1 ((NE*3)/256)
#define GEMM_SMEM (2*64*164*4)
__global__ void __launch_bounds__(256) k_gemm(){
    bool one = blockIdx.x < NB1;
    const uint2* Ag  = (const uint2*)(one ? g_V1p : g_V2p);
    const uint4* Bh4 = (const uint4*)(one ? g_WvBh1 : g_WvBh2);
    const uint4* Bl4 = (const uint4*)(one ? g_WvBl1 : g_WvBl2);
    float* C = one ? g_C1 : g_C2;
    long rowbase = one ? (long)blockIdx.x*256 : (long)(blockIdx.x-NB1)*256;

    extern __shared__ uint32_t smg[];
    uint32_t* sBh = smg;              // [64][164]
    uint32_t* sBl = smg + 64*164;
    int t=threadIdx.x;
    for(int q=t;q<2560;q+=256){
        uint4 vh=Bh4[q], vl=Bl4[q];
        int w0=q*4, n=w0/160, p=w0-n*160, base=n*164+p;
        sBh[base]=vh.x; sBh[base+1]=vh.y; sBh[base+2]=vh.z; sBh[base+3]=vh.w;
        sBl[base]=vl.x; sBl[base+1]=vl.y; sBl[base+2]=vl.z; sBl[base+3]=vl.w;
    }
    __syncthreads();

    int w=t>>5, lane=t&31;
    int g=lane>>2, tg=lane&3;
    const uint32_t* bh = sBh + g*164 + tg;
    const uint32_t* bl = sBl + g*164 + tg;
    const float sc = 0.05590169943749474f;

    #pragma unroll
    for(int rt=0;rt<2;rt++){
        long row0 = rowbase + w*32 + rt*16;
        float acc[8][4];
        #pragma unroll
        for(int i=0;i<8;i++){ acc[i][0]=0.f; acc[i][1]=0.f; acc[i][2]=0.f; acc[i][3]=0.f; }
        const uint2* arow0 = Ag + (row0+g  )*160 + tg;
        const uint2* arow1 = Ag + (row0+g+8)*160 + tg;

        #pragma unroll 2
        for(int kt=0; kt<20; kt++){
            uint2 q0 = arow0[kt*8];
            uint2 q2 = arow0[kt*8+4];
            uint2 q1 = arow1[kt*8];
            uint2 q3 = arow1[kt*8+4];
            uint32_t a0h=__byte_perm(q0.x,q0.y,0x5410), a0l=__byte_perm(q0.x,q0.y,0x7632);
            uint32_t a1h=__byte_perm(q1.x,q1.y,0x5410), a1l=__byte_perm(q1.x,q1.y,0x7632);
            uint32_t a2h=__byte_perm(q2.x,q2.y,0x5410), a2l=__byte_perm(q2.x,q2.y,0x7632);
            uint32_t a3h=__byte_perm(q3.x,q3.y,0x5410), a3l=__byte_perm(q3.x,q3.y,0x7632);
            #pragma unroll
            for(int nt=0;nt<8;nt++){
                int bi = nt*8*164 + kt*8;
                uint32_t b0h=bh[bi],  b1h=bh[bi+4];
                uint32_t b0l=bl[bi],  b1l=bl[bi+4];
                mma16816(acc[nt], a0h,a1h,a2h,a3h, b0h,b1h);
                mma16816(acc[nt], a0h,a1h,a2h,a3h, b0l,b1l);
                mma16816(acc[nt], a0l,a1l,a2l,a3l, b0h,b1h);
            }
        }
        float* c0 = C + (row0+g  )*64 + tg*2;
        float* c1 = C + (row0+g+8)*64 + tg*2;
        #pragma unroll
        for(int nt=0;nt<8;nt++){
            *(float2*)(c0 + nt*8) = make_float2(acc[nt][0]*sc, acc[nt][1]*sc);
            *(float2*)(c1 + nt*8) = make_float2(acc[nt][2]*sc, acc[nt][3]*sc);
        }
    }
}

// ---------------- fused 3-layer MMA MLP (256 thr, 128 edges/block; pad-132/36 B rows) ----------------
#define MLP_SMEM ((2*64*132 + 4*64*36)*4)
__global__ void __launch_bounds__(256) k_mlpmma(float* __restrict__ xout){
    extern __shared__ uint32_t sm[];
    uint32_t* sW1h = sm;                    // [64][132]
    uint32_t* sW1l = sm + 64*132;
    uint32_t* sW2h = sm + 2*64*132;         // [64][36]
    uint32_t* sW2l = sW2h + 64*36;
    uint32_t* sW3h = sW2l + 64*36;
    uint32_t* sW3l = sW3h + 64*36;
    int t=threadIdx.x;
    for(int q=t;q<2048;q+=256){
        uint4 vh=((const uint4*)g_W1h)[q], vl=((const uint4*)g_W1l)[q];
        int w0=q*4, n=w0>>7, p=w0&127, base=n*132+p;
        sW1h[base]=vh.x; sW1h[base+1]=vh.y; sW1h[base+2]=vh.z; sW1h[base+3]=vh.w;
        sW1l[base]=vl.x; sW1l[base+1]=vl.y; sW1l[base+2]=vl.z; sW1l[base+3]=vl.w;
    }
    for(int q=t;q<512;q+=256){
        int w0=q*4, n=w0>>5, p=w0&31, base=n*36+p;
        uint4 v2h=((const uint4*)g_W2h)[q], v2l=((const uint4*)g_W2l)[q];
        uint4 v3h=((const uint4*)g_W3h)[q], v3l=((const uint4*)g_W3l)[q];
        sW2h[base]=v2h.x; sW2h[base+1]=v2h.y; sW2h[base+2]=v2h.z; sW2h[base+3]=v2h.w;
        sW2l[base]=v2l.x; sW2l[base+1]=v2l.y; sW2l[base+2]=v2l.z; sW2l[base+3]=v2l.w;
        sW3h[base]=v3h.x; sW3h[base+1]=v3h.y; sW3h[base+2]=v3h.z; sW3h[base+3]=v3h.w;
        sW3l[base]=v3l.x; sW3l[base+1]=v3l.y; sW3l[base+2]=v3l.z; sW3l[base+3]=v3l.w;
    }
    __syncthreads();

    int w=t>>5, lane=t&31, g=lane>>2, tg=lane&3;
    int e0 = blockIdx.x*128 + w*16;
    float inv_actc = 1.0f/g_actc;

    float acc[8][4];
    #pragma unroll
    for(int i=0;i<8;i++){ acc[i][0]=0.f; acc[i][1]=0.f; acc[i][2]=0.f; acc[i][3]=0.f; }
    const uint2* Ap = (const uint2*)g_hp;
    const uint2* ar0 = Ap + (e0+g  )*128 + tg;
    const uint2* ar1 = Ap + (e0+g+8)*128 + tg;
    #pragma unroll 2
    for(int kt=0;kt<16;kt++){
        uint2 q0=ar0[kt*8],   q2=ar0[kt*8+4];
        uint2 q1=ar1[kt*8],   q3=ar1[kt*8+4];
        uint32_t a0h=__byte_perm(q0.x,q0.y,0x5410), a0l=__byte_perm(q0.x,q0.y,0x7632);
        uint32_t a1h=__byte_perm(q1.x,q1.y,0x5410), a1l=__byte_perm(q1.x,q1.y,0x7632);
        uint32_t a2h=__byte_perm(q2.x,q2.y,0x5410), a2l=__byte_perm(q2.x,q2.y,0x7632);
        uint32_t a3h=__byte_perm(q3.x,q3.y,0x5410), a3l=__byte_perm(q3.x,q3.y,0x7632);
        #pragma unroll
        for(int nt=0;nt<8;nt++){
            int bi=(nt*8+g)*132 + kt*8 + tg;
            uint32_t b0h=sW1h[bi], b1h=sW1h[bi+4];
            uint32_t b0l=sW1l[bi], b1l=sW1l[bi+4];
            mma16816(acc[nt], a0h,a1h,a2h,a3h, b0h,b1h);
            mma16816(acc[nt], a0h,a1h,a2h,a3h, b0l,b1l);
            mma16816(acc[nt], a0l,a1l,a2l,a3l, b0h,b1h);
        }
    }
    float v[8][4];
    #pragma unroll
    for(int nt=0;nt<8;nt++)
        #pragma unroll
        for(int j=0;j<4;j++){
            float a = acc[nt][j]*0.0625f;
            v[nt][j] = a*__fdividef(1.f, 1.f+__expf(-a))*inv_actc;
        }

    #pragma unroll
    for(int i=0;i<8;i++){ acc[i][0]=0.f; acc[i][1]=0.f; acc[i][2]=0.f; acc[i][3]=0.f; }
    #pragma unroll
    for(int kt=0;kt<4;kt++){
        uint32_t a0h,a0l,a1h,a1l,a2h,a2l,a3h,a3l;
        split2(v[2*kt][0],  v[2*kt][1],   a0h,a0l);
        split2(v[2*kt][2],  v[2*kt][3],   a1h,a1l);
        split2(v[2*kt+1][0],v[2*kt+1][1], a2h,a2l);
        split2(v[2*kt+1][2],v[2*kt+1][3], a3h,a3l);
        #pragma unroll
        for(int nt=0;nt<8;nt++){
            int bi=(nt*8+g)*36 + kt*8 + tg;
            uint32_t b0h=sW2h[bi], b1h=sW2h[bi+4];
            uint32_t b0l=sW2l[bi], b1l=sW2l[bi+4];
            mma16816(acc[nt], a0h,a1h,a2h,a3h, b0h,b1h);
            mma16816(acc[nt], a0h,a1h,a2h,a3h, b0l,b1l);
            mma16816(acc[nt], a0l,a1l,a2l,a3l, b0h,b1h);
        }
    }
    #pragma unroll
    for(int nt=0;nt<8;nt++)
        #pragma unroll
        for(int j=0;j<4;j++){
            float a = acc[nt][j]*0.125f;
            v[nt][j] = a*__fdividef(1.f, 1.f+__expf(-a))*inv_actc;
        }

    #pragma unroll
    for(int i=0;i<8;i++){ acc[i][0]=0.f; acc[i][1]=0.f; acc[i][2]=0.f; acc[i][3]=0.f; }
    #pragma unroll
    for(int kt=0;kt<4;kt++){
        uint32_t a0h,a0l,a1h,a1l,a2h,a2l,a3h,a3l;
        split2(v[2*kt][0],  v[2*kt][1],   a0h,a0l);
        split2(v[2*kt][2],  v[2*kt][3],   a1h,a1l);
        split2(v[2*kt+1][0],v[2*kt+1][1], a2h,a2l);
        split2(v[2*kt+1][2],v[2*kt+1][3], a3h,a3l);
        #pragma unroll
        for(int nt=0;nt<8;nt++){
            int bi=(nt*8+g)*36 + kt*8 + tg;
            uint32_t b0h=sW3h[bi], b1h=sW3h[bi+4];
            uint32_t b0l=sW3l[bi], b1l=sW3l[bi+4];
            mma16816(acc[nt], a0h,a1h,a2h,a3h, b0h,b1h);
            mma16816(acc[nt], a0h,a1h,a2h,a3h, b0l,b1l);
            mma16816(acc[nt], a0l,a1l,a2l,a3l, b0h,b1h);
        }
    }

    int eg0=e0+g, eg1=e0+g+8;
    float d0=g_d[eg0], d1=g_d[eg1];
    float f0=0.f, f1=0.f;
    if(d0<1.f){ float d3=d0*d0*d0, d6=d3*d3, d7=d6*d0, d8=d7*d0; f0=(1.f-28.f*d6+48.f*d7-21.f*d8)*0.125f; }
    if(d1<1.f){ float d3=d1*d1*d1, d6=d3*d3, d7=d6*d1, d8=d7*d1; f1=(1.f-28.f*d6+48.f*d7-21.f*d8)*0.125f; }
    float* o0 = xout + eg0*64 + tg*2;
    float* o1 = xout + eg1*64 + tg*2;
    #pragma unroll
    for(int nt=0;nt<8;nt++){
        *(float2*)(o0 + nt*8) = make_float2(acc[nt][0]*f0, acc[nt][1]*f0);
        *(float2*)(o1 + nt*8) = make_float2(acc[nt][2]*f1, acc[nt][3]*f1);
    }
}

// ---------------- interleave staging -> V_out layout ----------------
__global__ void k_pack(float* __restrict__ vout){
    __shared__ float sC1[3072];
    __shared__ float sC2[5120];
    int t=threadIdx.x; long e0 = (long)blockIdx.x*16;
    const float4* c1 = (const float4*)(g_C1 + e0*3*64);
    const float4* c2 = (const float4*)(g_C2 + e0*5*64);
    for(int q=t;q<768;q+=256)  ((float4*)sC1)[q]=c1[q];
    for(int q=t;q<1280;q+=256) ((float4*)sC2)[q]=c2[q];
    __syncthreads();
    for(int le=0;le<16;le++){
        float* op = vout + (e0+le)*576;
        #pragma unroll
        for(int pass=0;pass<3;pass++){
            int off = t + pass*256;
            if(off<576){
                int o = off/9, c = off - o*9;
                float v = 0.f;
                if(c>=1 && c<4)      v = sC1[(le*3 + c-1)*64 + o];
                else if(c>=4)        v = sC2[(le*5 + c-4)*64 + o];
                op[off]=v;
            }
        }
    }
}

// ---------------- launch ----------------
extern "C" void kernel_launch(void* const* d_in, const int* in_sizes, int n_in,
                              void* d_out, int out_size){
    const float* vectors = (const float*)d_in[0];
    const float* x       = (const float*)d_in[1];
    const float* V       = (const float*)d_in[2];
    const int*   senders = (const int*)  d_in[3];
    const float* Ww      = (const float*)d_in[4];
    const float* W1      = (const float*)d_in[5];
    const float* W2      = (const float*)d_in[6];
    const float* W3      = (const float*)d_in[7];
    const float* Wv1     = (const float*)d_in[8];
    const float* Wv2     = (const float*)d_in[9];
    float* out  = (float*)d_out;
    float* vout = out + (size_t)NE*64;

    host_compute_constants();
    cudaMemcpyToSymbolAsync(g_cg,   s_cg_host,    sizeof(s_cg_host), 0, cudaMemcpyHostToDevice, 0);
    cudaMemcpyToSymbolAsync(g_actc, &s_actc_host, sizeof(float),     0, cudaMemcpyHostToDevice, 0);

    cudaFuncSetAttribute(k_gemm,   cudaFuncAttributeMaxDynamicSharedMemorySize, GEMM_SMEM);
    cudaFuncSetAttribute(k_mlpmma, cudaFuncAttributeMaxDynamicSharedMemorySize, MLP_SMEM);

    k_prep<<<PREP_WPACK_BLOCKS + NE/4,256>>>(Wv1, Wv2, W1, W2, W3, Ww, x, vectors, senders);
    k_wmma<<<NE/128,256>>>();
    k_scan<<<1,1024>>>();
    k_fill<<<64,256>>>(senders);
    k_gather<<<NNODES/4,128>>>();
    k_tp<<<NE/8,256>>>(V, senders);
    k_gemm<<<(NE*8)/256,256,GEMM_SMEM>>>();
    k_mlpmma<<<NE/128,256,MLP_SMEM>>>(out);
    k_pack<<<NE/16,256>>>(vout);
}

// round 17
// speedup vs baseline: 1.8098x; 1.0188x over previous
#include <cuda_runtime.h>
#include <cuda_bf16.h>
#include <math.h>
#include <stdint.h>

#define NE 16384
#define NNODES 1024
#define PI_D 3.14159265358979323846

// ---------------- scratch ----------------
__device__ float    g_cg[573];
__device__ float    g_actc;
__device__ float    g_node[NNODES * 64 * 16];
__device__ float    g_d[NE];
__device__ float    g_w[NE * 64];
__device__ float    g_Yt[NE * 16];
__device__ __align__(16) uint32_t g_hp[NE * 256];       // packed MLP input [e][k]
__device__ __align__(16) uint32_t g_V1p[NE * 3 * 320];  // packed (hi bf16 | lo bf16<<16), row=(e*3+i), K=320
__device__ __align__(16) uint32_t g_V2p[NE * 5 * 320];  // row=(e*5+k)
__device__ __align__(16) uint32_t g_WvBh1[64 * 160];
__device__ __align__(16) uint32_t g_WvBl1[64 * 160];
__device__ __align__(16) uint32_t g_WvBh2[64 * 160];
__device__ __align__(16) uint32_t g_WvBl2[64 * 160];
__device__ __align__(16) uint32_t g_W1h[64 * 128];
__device__ __align__(16) uint32_t g_W1l[64 * 128];
__device__ __align__(16) uint32_t g_W2h[64 * 32];
__device__ __align__(16) uint32_t g_W2l[64 * 32];
__device__ __align__(16) uint32_t g_W3h[64 * 32];
__device__ __align__(16) uint32_t g_W3l[64 * 32];
__device__ __align__(16) uint32_t g_Wwh[64 * 32];
__device__ __align__(16) uint32_t g_Wwl[64 * 32];
__device__ float    g_C1[NE * 3 * 64];
__device__ float    g_C2[NE * 5 * 64];
__device__ int      g_cnt[NNODES];      // zero-init at load; k_scan re-zeroes after read
__device__ int      g_off[NNODES + 1];
__device__ int      g_cur[NNODES];
__device__ int      g_eidx[NE];

// ---------------- device helpers ----------------
__device__ __forceinline__ uint32_t pack_hl(float v){
    __nv_bfloat16 h = __float2bfloat16(v);
    float hf = __bfloat162float(h);
    __nv_bfloat16 l = __float2bfloat16(v - hf);
    return (uint32_t)__bfloat16_as_ushort(h) | ((uint32_t)__bfloat16_as_ushort(l) << 16);
}
__device__ __forceinline__ void split2(float v0, float v1, uint32_t& h, uint32_t& l){
    uint32_t p0 = pack_hl(v0), p1 = pack_hl(v1);
    h = __byte_perm(p0, p1, 0x5410);
    l = __byte_perm(p0, p1, 0x7632);
}
__device__ __forceinline__ void mma16816(float* d,
        uint32_t a0, uint32_t a1, uint32_t a2, uint32_t a3,
        uint32_t b0, uint32_t b1){
    asm volatile(
        "mma.sync.aligned.m16n8k16.row.col.f32.bf16.bf16.f32 "
        "{%0,%1,%2,%3}, {%4,%5,%6,%7}, {%8,%9}, {%0,%1,%2,%3};"
        : "+f"(d[0]), "+f"(d[1]), "+f"(d[2]), "+f"(d[3])
        : "r"(a0), "r"(a1), "r"(a2), "r"(a3), "r"(b0), "r"(b1));
}

// ---------------- host-side CG + ACT_C ----------------
static const int h_l1[13]  = {0,1,2, 0,1,1,2,3, 0,1,2,2,3};
static const int h_l2[13]  = {0,1,2, 1,0,2,1,2, 2,1,0,2,1};
static const int h_l3[13]  = {0,0,0, 1,1,1,1,1, 2,2,2,2,2};
static const int h_offs[14]= {0,1,10,35,44,53,98,143,248,273,318,343,468,573};

static double h_dfact(int n){ double r=1.0; while(n>1){ r*=(double)n; n-=2; } return r; }
static double h_mono(int a,int b,int c){
    if((a&1)||(b&1)||(c&1)) return 0.0;
    return 4.0*PI_D*h_dfact(a-1)*h_dfact(b-1)*h_dfact(c-1)/h_dfact(a+b+c+1);
}
static int h_sh(int l,int m,double* c,int (*ex)[3]){
    double S3=sqrt(3.0), S5=sqrt(5.0), S15=sqrt(15.0);
    double C33=sqrt(70.0)/4.0, C32=sqrt(105.0)/2.0, C31=sqrt(42.0)/4.0, C30=sqrt(7.0)/2.0, CX=sqrt(105.0);
#define TT(t,cc,a,b,cz) { c[t]=(cc); ex[t][0]=(a); ex[t][1]=(b); ex[t][2]=(cz); }
    if(l==0){ TT(0,1.0,0,0,0); return 1; }
    if(l==1){
        if(m==0){ TT(0,S3,1,0,0); } else if(m==1){ TT(0,S3,0,1,0); } else { TT(0,S3,0,0,1); }
        return 1;
    }
    if(l==2){
        switch(m){
            case 0: TT(0,S15,1,1,0); return 1;
            case 1: TT(0,S15,0,1,1); return 1;
            case 2: TT(0,1.5*S5,0,0,2); TT(1,-0.5*S5,0,0,0); return 2;
            case 3: TT(0,S15,1,0,1); return 1;
            default: TT(0,0.5*S15,2,0,0); TT(1,-0.5*S15,0,2,0); return 2;
        }
    }
    switch(m){
        case 0: TT(0,3.0*C33,2,1,0); TT(1,-C33,0,3,0); return 2;
        case 1: TT(0,CX,1,1,1); return 1;
        case 2: TT(0,5.0*C31,0,1,2); TT(1,-C31,0,1,0); return 2;
        case 3: TT(0,5.0*C30,0,0,3); TT(1,-3.0*C30,0,0,1); return 2;
        case 4: TT(0,5.0*C31,1,0,2); TT(1,-C31,1,0,0); return 2;
        case 5: TT(0,C32,2,0,1); TT(1,-C32,0,2,1); return 2;
        default: TT(0,C33,3,0,0); TT(1,-3.0*C33,1,2,0); return 2;
    }
#undef TT
}

static float s_cg_host[573];
static float s_actc_host;

static void host_compute_constants(){
    double raw[573];
    for(int p=0;p<13;p++){
        int l1=h_l1[p], l2=h_l2[p], l3=h_l3[p];
        int n1=2*l1+1, n2=2*l2+1, n3=2*l3+1;
        int off=h_offs[p];
        for(int i=0;i<n1;i++) for(int j=0;j<n2;j++) for(int k=0;k<n3;k++){
            double c1[2],c2[2],c3[2]; int e1[2][3],e2[2][3],e3[2][3];
            int t1=h_sh(l1,i,c1,e1), t2=h_sh(l2,j,c2,e2), t3=h_sh(l3,k,c3,e3);
            double v=0.0;
            for(int a=0;a<t1;a++) for(int b=0;b<t2;b++) for(int cc=0;cc<t3;cc++)
                v += c1[a]*c2[b]*c3[cc]*h_mono(e1[a][0]+e2[b][0]+e3[cc][0],
                                              e1[a][1]+e2[b][1]+e3[cc][1],
                                              e1[a][2]+e2[b][2]+e3[cc][2]);
            raw[off + (i*n2+j)*n3 + k] = v/(4.0*PI_D);
        }
        double s=0.0;
        for(int q=off;q<h_offs[p+1];q++) s += raw[q]*raw[q];
        double sc = sqrt((double)(2*l3+1))/sqrt(s);
        for(int q=off;q<h_offs[p+1];q++) s_cg_host[q] = (float)(raw[q]*sc);
    }
    double step = 24.0/200000.0, acc=0.0;
    for(int i=0;i<=200000;i++){
        double z = -12.0 + step*(double)i;
        double phi = exp(-0.5*z*z)*0.39894228040143267794;
        double sl = z/(1.0+exp(-z));
        acc += sl*sl*phi;
    }
    s_actc_host = (float)sqrt(acc*step);
}

// ---------------- merged prep: weight packing (blocks < 136) + per-edge (blocks >= 136) ----------------
#define PREP_WPACK_BLOCKS 136
__global__ void k_prep(const float* __restrict__ Wv1, const float* __restrict__ Wv2,
                       const float* __restrict__ W1,  const float* __restrict__ W2,
                       const float* __restrict__ W3,  const float* __restrict__ Ww,
                       const float* __restrict__ x,   const float* __restrict__ vec,
                       const int* __restrict__ senders){
    if(blockIdx.x < PREP_WPACK_BLOCKS){
        int i = blockIdx.x*256+threadIdx.x;
        const float* W; uint32_t *Bh, *Bl; int j, np;
        if(i < 10240){ W=Wv1; Bh=g_WvBh1; Bl=g_WvBl1; j=i; np=160; }
        else if(i < 20480){ W=Wv2; Bh=g_WvBh2; Bl=g_WvBl2; j=i-10240; np=160; }
        else if(i < 28672){ W=W1; Bh=g_W1h; Bl=g_W1l; j=i-20480; np=128; }
        else if(i < 30720){ W=W2; Bh=g_W2h; Bl=g_W2l; j=i-28672; np=32; }
        else if(i < 32768){ W=W3; Bh=g_W3h; Bl=g_W3l; j=i-30720; np=32; }
        else if(i < 34816){ W=Ww; Bh=g_Wwh; Bl=g_Wwl; j=i-32768; np=32; }
        else return;
        int n=j/np, p=j-n*np;
        uint32_t p0 = pack_hl(W[(2*p  )*64 + n]);
        uint32_t p1 = pack_hl(W[(2*p+1)*64 + n]);
        Bh[j] = __byte_perm(p0, p1, 0x5410);
        Bl[j] = __byte_perm(p0, p1, 0x7632);
        return;
    }
    int i = (blockIdx.x - PREP_WPACK_BLOCKS)*256 + threadIdx.x;   // over NE*64
    int e = i>>6, k = i&63;
    g_hp[e*256+k] = pack_hl(x[i]);
    if(k==0){
        atomicAdd(&g_cnt[senders[e]],1);
        float vx=vec[e*3+0], vy=vec[e*3+1], vz=vec[e*3+2];
        float d = sqrtf(vx*vx+vy*vy+vz*vz);
        g_d[e]=d;
        float X=vx/d, Y=vy/d, Z=vz/d;
        const float S3=1.7320508075688772f, S5=2.2360679774997896f, S15=3.8729833462074170f;
        const float C33=2.0916500663351889f, C32=5.1234753829797990f, C31=1.6201851746019651f;
        const float C30=1.3228756555322954f, CX=10.246950765959598f;
        float y[16];
        y[0]=1.f; y[1]=S3*X; y[2]=S3*Y; y[3]=S3*Z;
        y[4]=S15*X*Y; y[5]=S15*Y*Z; y[6]=0.5f*S5*(3.f*Z*Z-1.f); y[7]=S15*X*Z; y[8]=0.5f*S15*(X*X-Y*Y);
        y[9]=C33*Y*(3.f*X*X-Y*Y); y[10]=CX*X*Y*Z; y[11]=C31*Y*(5.f*Z*Z-1.f);
        y[12]=C30*Z*(5.f*Z*Z-3.f); y[13]=C31*X*(5.f*Z*Z-1.f); y[14]=C32*Z*(X*X-Y*Y); y[15]=C33*X*(X*X-3.f*Y*Y);
        float4* yp=(float4*)(g_Yt+e*16);
        yp[0]=make_float4(y[0],y[1],y[2],y[3]);
        yp[1]=make_float4(y[4],y[5],y[6],y[7]);
        yp[2]=make_float4(y[8],y[9],y[10],y[11]);
        yp[3]=make_float4(y[12],y[13],y[14],y[15]);
    }
}

// ---------------- CSR scan (+ self-reset of g_cnt) and fill ----------------
__global__ void k_scan(){
    __shared__ int s[1024];
    int t=threadIdx.x;
    int c = g_cnt[t];
    g_cnt[t] = 0;                      // reset for next replay (module-load value is 0)
    s[t]=c; __syncthreads();
    for(int o=1;o<1024;o<<=1){
        int v = (t>=o)? s[t-o] : 0;
        __syncthreads(); s[t]+=v; __syncthreads();
    }
    int incl = s[t];
    g_off[t] = incl - c;
    g_cur[t] = incl - c;
    if(t==1023) g_off[1024]=incl;
}
__global__ void k_fill(const int* __restrict__ senders){
    int e=blockIdx.x*256+threadIdx.x; if(e>=NE) return;
    int s=senders[e];
    int pos=atomicAdd(&g_cur[s],1);
    g_eidx[pos]=e;
}

// ---------------- w = x@Ww / 8 via MMA (256 thr, 128 edges/block; pad-36 B rows) ----------------
__global__ void __launch_bounds__(256) k_wmma(){
    __shared__ uint32_t sBh[64*36], sBl[64*36];
    int t=threadIdx.x;
    for(int q=t;q<512;q+=256){
        uint4 vh=((const uint4*)g_Wwh)[q], vl=((const uint4*)g_Wwl)[q];
        int w0=q*4, n=w0>>5, p=w0&31, base=n*36+p;
        sBh[base]=vh.x; sBh[base+1]=vh.y; sBh[base+2]=vh.z; sBh[base+3]=vh.w;
        sBl[base]=vl.x; sBl[base+1]=vl.y; sBl[base+2]=vl.z; sBl[base+3]=vl.w;
    }
    __syncthreads();

    int w=t>>5, lane=t&31, g=lane>>2, tg=lane&3;
    int e0 = blockIdx.x*128 + w*16;

    float acc[8][4];
    #pragma unroll
    for(int i=0;i<8;i++){ acc[i][0]=0.f; acc[i][1]=0.f; acc[i][2]=0.f; acc[i][3]=0.f; }
    const uint2* Ap = (const uint2*)g_hp;
    const uint2* ar0 = Ap + (e0+g  )*128 + tg;
    const uint2* ar1 = Ap + (e0+g+8)*128 + tg;
    #pragma unroll
    for(int kt=0;kt<4;kt++){
        uint2 q0=ar0[kt*8],   q2=ar0[kt*8+4];
        uint2 q1=ar1[kt*8],   q3=ar1[kt*8+4];
        uint32_t a0h=__byte_perm(q0.x,q0.y,0x5410), a0l=__byte_perm(q0.x,q0.y,0x7632);
        uint32_t a1h=__byte_perm(q1.x,q1.y,0x5410), a1l=__byte_perm(q1.x,q1.y,0x7632);
        uint32_t a2h=__byte_perm(q2.x,q2.y,0x5410), a2l=__byte_perm(q2.x,q2.y,0x7632);
        uint32_t a3h=__byte_perm(q3.x,q3.y,0x5410), a3l=__byte_perm(q3.x,q3.y,0x7632);
        #pragma unroll
        for(int nt=0;nt<8;nt++){
            int bi=(nt*8+g)*36 + kt*8 + tg;
            uint32_t b0h=sBh[bi], b1h=sBh[bi+4];
            uint32_t b0l=sBl[bi], b1l=sBl[bi+4];
            mma16816(acc[nt], a0h,a1h,a2h,a3h, b0h,b1h);
            mma16816(acc[nt], a0h,a1h,a2h,a3h, b0l,b1l);
            mma16816(acc[nt], a0l,a1l,a2l,a3l, b0h,b1h);
        }
    }
    int eg0=e0+g, eg1=e0+g+8;
    float* o0 = g_w + eg0*64 + tg*2;
    float* o1 = g_w + eg1*64 + tg*2;
    #pragma unroll
    for(int nt=0;nt<8;nt++){
        *(float2*)(o0 + nt*8) = make_float2(acc[nt][0]*0.125f, acc[nt][1]*0.125f);
        *(float2*)(o1 + nt*8) = make_float2(acc[nt][2]*0.125f, acc[nt][3]*0.125f);
    }
}

// ---------------- atomic-free node aggregation: warp per node ----------------
__global__ void __launch_bounds__(128) k_gather(){
    int t=threadIdx.x, w=t>>5, lane=t&31;
    int b = blockIdx.x*4 + w;
    int beg=g_off[b], end=g_off[b+1];
    float acc0[16], acc1[16];
    #pragma unroll
    for(int k=0;k<16;k++){ acc0[k]=0.f; acc1[k]=0.f; }
    for(int j=beg;j<end;j++){
        int e=g_eidx[j];
        float2 wv = *(const float2*)(g_w + (size_t)e*64 + lane*2);
        const float4* yp = (const float4*)(g_Yt + (size_t)e*16);
        float4 y0=yp[0], y1=yp[1], y2=yp[2], y3=yp[3];
        float Y[16] = {y0.x,y0.y,y0.z,y0.w, y1.x,y1.y,y1.z,y1.w,
                       y2.x,y2.y,y2.z,y2.w, y3.x,y3.y,y3.z,y3.w};
        #pragma unroll
        for(int k=0;k<16;k++){ acc0[k]+=wv.x*Y[k]; acc1[k]+=wv.y*Y[k]; }
    }
    float4* np0 = (float4*)(g_node + ((size_t)b*64 + lane*2)*16);
    np0[0]=make_float4(acc0[0],acc0[1],acc0[2],acc0[3]);
    np0[1]=make_float4(acc0[4],acc0[5],acc0[6],acc0[7]);
    np0[2]=make_float4(acc0[8],acc0[9],acc0[10],acc0[11]);
    np0[3]=make_float4(acc0[12],acc0[13],acc0[14],acc0[15]);
    np0[4]=make_float4(acc1[0],acc1[1],acc1[2],acc1[3]);
    np0[5]=make_float4(acc1[4],acc1[5],acc1[6],acc1[7]);
    np0[6]=make_float4(acc1[8],acc1[9],acc1[10],acc1[11]);
    np0[7]=make_float4(acc1[12],acc1[13],acc1[14],acc1[15]);
}

// ---------------- 13 CG tensor-product paths: parity-sparse, 8 edges/block, 2 ch/thread ----------------
#define PTP_PAR1(i) ((i)==0?4:((i)==1?2:1))
#define PTP_PAR2(j) ((j)==0?6:((j)==1?3:((j)==2?0:((j)==3?5:0))))
#define PTP_PAR3(i) ((i)==0?2:((i)==1?7:((i)==2?2:((i)==3?1:((i)==4?4:((i)==5?1:4))))))
__global__ void k_tp(const float* __restrict__ V, const int* __restrict__ senders){
    __shared__ float cg[573];
    int t=threadIdx.x;
    for(int q=t;q<573;q+=256) cg[q]=g_cg[q];
    __syncthreads();
    int e = blockIdx.x*8 + (t>>5);
    int q2 = t&31;
    int n0 = q2*2;
    int s = senders[e];
    float A[2][16], B[2][9];
    #pragma unroll
    for(int cc=0;cc<2;cc++){
        const float4* ap4 = (const float4*)(g_node + ((size_t)s*64+n0+cc)*16);
        float4 a0=ap4[0], a1=ap4[1], a2=ap4[2], a3=ap4[3];
        A[cc][0]=a0.x*0.25f; A[cc][1]=a0.y*0.25f; A[cc][2]=a0.z*0.25f; A[cc][3]=a0.w*0.25f;
        A[cc][4]=a1.x*0.25f; A[cc][5]=a1.y*0.25f; A[cc][6]=a1.z*0.25f; A[cc][7]=a1.w*0.25f;
        A[cc][8]=a2.x*0.25f; A[cc][9]=a2.y*0.25f; A[cc][10]=a2.z*0.25f; A[cc][11]=a2.w*0.25f;
        A[cc][12]=a3.x*0.25f; A[cc][13]=a3.y*0.25f; A[cc][14]=a3.z*0.25f; A[cc][15]=a3.w*0.25f;
        const float* bp = V + ((size_t)e*64+n0+cc)*9;
        #pragma unroll
        for(int j=0;j<9;j++) B[cc][j]=bp[j];
    }

    {
        float s0[2], s1[2]={0.f,0.f}, s2[2]={0.f,0.f};
        float c0 = cg[0];
        s0[0]=A[0][0]*B[0][0]*c0; s0[1]=A[1][0]*B[1][0]*c0;
        #pragma unroll
        for(int i=0;i<3;i++)
            #pragma unroll
            for(int j=0;j<3;j++) if((PTP_PAR1(i)^PTP_PAR1(j))==0){ float c=cg[1+i*3+j];
                s1[0]+=A[0][1+i]*B[0][1+j]*c; s1[1]+=A[1][1+i]*B[1][1+j]*c; }
        #pragma unroll
        for(int i=0;i<5;i++)
            #pragma unroll
            for(int j=0;j<5;j++) if((PTP_PAR2(i)^PTP_PAR2(j))==0){ float c=cg[10+i*5+j];
                s2[0]+=A[0][4+i]*B[0][4+j]*c; s2[1]+=A[1][4+i]*B[1][4+j]*c; }
        int hb = e*256 + 64 + n0*3;
        g_hp[hb+0]=pack_hl(s0[0]); g_hp[hb+1]=pack_hl(s1[0]); g_hp[hb+2]=pack_hl(s2[0]);
        g_hp[hb+3]=pack_hl(s0[1]); g_hp[hb+4]=pack_hl(s1[1]); g_hp[hb+5]=pack_hl(s2[1]);
    }

    {
        float o[5][3][2];
        #pragma unroll
        for(int p=0;p<5;p++)
            #pragma unroll
            for(int i=0;i<3;i++){ o[p][i][0]=0.f; o[p][i][1]=0.f; }
        #pragma unroll
        for(int j=0;j<3;j++){
            float ab0=A[0][0]*B[0][1+j], ab1=A[1][0]*B[1][1+j];
            #pragma unroll
            for(int k=0;k<3;k++) if((PTP_PAR1(j)^PTP_PAR1(k))==0){ float c=cg[35+j*3+k]; o[0][k][0]+=ab0*c; o[0][k][1]+=ab1*c; }
        }
        #pragma unroll
        for(int i=0;i<3;i++){
            float ab0=A[0][1+i]*B[0][0], ab1=A[1][1+i]*B[1][0];
            #pragma unroll
            for(int k=0;k<3;k++) if((PTP_PAR1(i)^PTP_PAR1(k))==0){ float c=cg[44+i*3+k]; o[1][k][0]+=ab0*c; o[1][k][1]+=ab1*c; }
        }
        #pragma unroll
        for(int i=0;i<3;i++)
            #pragma unroll
            for(int j=0;j<5;j++){
                float ab0=A[0][1+i]*B[0][4+j], ab1=A[1][1+i]*B[1][4+j];
                int c0i=53+(i*5+j)*3;
                #pragma unroll
                for(int k=0;k<3;k++) if((PTP_PAR1(i)^PTP_PAR2(j)^PTP_PAR1(k))==0){ float c=cg[c0i+k]; o[2][k][0]+=ab0*c; o[2][k][1]+=ab1*c; }
            }
        #pragma unroll
        for(int i=0;i<5;i++)
            #pragma unroll
            for(int j=0;j<3;j++){
                float ab0=A[0][4+i]*B[0][1+j], ab1=A[1][4+i]*B[1][1+j];
                int c0i=98+(i*3+j)*3;
                #pragma unroll
                for(int k=0;k<3;k++) if((PTP_PAR2(i)^PTP_PAR1(j)^PTP_PAR1(k))==0){ float c=cg[c0i+k]; o[3][k][0]+=ab0*c; o[3][k][1]+=ab1*c; }
            }
        #pragma unroll
        for(int i=0;i<7;i++)
            #pragma unroll
            for(int j=0;j<5;j++){
                float ab0=A[0][9+i]*B[0][4+j], ab1=A[1][9+i]*B[1][4+j];
                int c0i=143+(i*5+j)*3;
                #pragma unroll
                for(int k=0;k<3;k++) if((PTP_PAR3(i)^PTP_PAR2(j)^PTP_PAR1(k))==0){ float c=cg[c0i+k]; o[4][k][0]+=ab0*c; o[4][k][1]+=ab1*c; }
            }
        #pragma unroll
        for(int p=0;p<5;p++)
            #pragma unroll
            for(int i=0;i<3;i++){
                int b = e*960 + i*320 + p*64 + n0;
                uint2 v; v.x=pack_hl(o[p][i][0]); v.y=pack_hl(o[p][i][1]);
                *(uint2*)(g_V1p + b) = v;
            }
    }

    {
        float o[5][5][2];
        #pragma unroll
        for(int p=0;p<5;p++)
            #pragma unroll
            for(int k=0;k<5;k++){ o[p][k][0]=0.f; o[p][k][1]=0.f; }
        #pragma unroll
        for(int j=0;j<5;j++){
            float ab0=A[0][0]*B[0][4+j], ab1=A[1][0]*B[1][4+j];
            int c0i=248+j*5;
            #pragma unroll
            for(int k=0;k<5;k++) if((PTP_PAR2(j)^PTP_PAR2(k))==0){ float c=cg[c0i+k]; o[0][k][0]+=ab0*c; o[0][k][1]+=ab1*c; }
        }
        #pragma unroll
        for(int i=0;i<3;i++)
            #pragma unroll
            for(int j=0;j<3;j++){
                float ab0=A[0][1+i]*B[0][1+j], ab1=A[1][1+i]*B[1][1+j];
                int c0i=273+(i*3+j)*5;
                #pragma unroll
                for(int k=0;k<5;k++) if((PTP_PAR1(i)^PTP_PAR1(j)^PTP_PAR2(k))==0){ float c=cg[c0i+k]; o[1][k][0]+=ab0*c; o[1][k][1]+=ab1*c; }
            }
        #pragma unroll
        for(int i=0;i<5;i++){
            float ab0=A[0][4+i]*B[0][0], ab1=A[1][4+i]*B[1][0];
            int c0i=318+i*5;
            #pragma unroll
            for(int k=0;k<5;k++) if((PTP_PAR2(i)^PTP_PAR2(k))==0){ float c=cg[c0i+k]; o[2][k][0]+=ab0*c; o[2][k][1]+=ab1*c; }
        }
        #pragma unroll
        for(int i=0;i<5;i++)
            #pragma unroll
            for(int j=0;j<5;j++){
                float ab0=A[0][4+i]*B[0][4+j], ab1=A[1][4+i]*B[1][4+j];
                int c0i=343+(i*5+j)*5;
                #pragma unroll
                for(int k=0;k<5;k++) if((PTP_PAR2(i)^PTP_PAR2(j)^PTP_PAR2(k))==0){ float c=cg[c0i+k]; o[3][k][0]+=ab0*c; o[3][k][1]+=ab1*c; }
            }
        #pragma unroll
        for(int i=0;i<7;i++)
            #pragma unroll
            for(int j=0;j<3;j++){
                float ab0=A[0][9+i]*B[0][1+j], ab1=A[1][9+i]*B[1][1+j];
                int c0i=468+(i*3+j)*5;
                #pragma unroll
                for(int k=0;k<5;k++) if((PTP_PAR3(i)^PTP_PAR1(j)^PTP_PAR2(k))==0){ float c=cg[c0i+k]; o[4][k][0]+=ab0*c; o[4][k][1]+=ab1*c; }
            }
        #pragma unroll
        for(int p=0;p<5;p++)
            #pragma unroll
            for(int k=0;k<5;k++){
                int b = e*1600 + k*320 + p*64 + n0;
                uint2 v; v.x=pack_hl(o[p][k][0]); v.y=pack_hl(o[p][k][1]);
                *(uint2*)(g_V2p + b) = v;
            }
    }
}

// ---------------- merged bf16-split GEMM (both o1 and o2; pad-164 B rows) ----------------
#define NB1 ((NE*3)/256)
#define GEMM_SMEM (2*64*164*4)
__global__ void __launch_bounds__(256) k_gemm(){
    bool one = blockIdx.x < NB1;
    const uint2* Ag  = (const uint2*)(one ? g_V1p : g_V2p);
    const uint4* Bh4 = (const uint4*)(one ? g_WvBh1 : g_WvBh2);
    const uint4* Bl4 = (const uint4*)(one ? g_WvBl1 : g_WvBl2);
    float* C = one ? g_C1 : g_C2;
    long rowbase = one ? (long)blockIdx.x*256 : (long)(blockIdx.x-NB1)*256;

    extern __shared__ uint32_t smg[];
    uint32_t* sBh = smg;              // [64][164]
    uint32_t* sBl = smg + 64*164;
    int t=threadIdx.x;
    for(int q=t;q<2560;q+=256){
        uint4 vh=Bh4[q], vl=Bl4[q];
        int w0=q*4, n=w0/160, p=w0-n*160, base=n*164+p;
        sBh[base]=vh.x; sBh[base+1]=vh.y; sBh[base+2]=vh.z; sBh[base+3]=vh.w;
        sBl[base]=vl.x; sBl[base+1]=vl.y; sBl[base+2]=vl.z; sBl[base+3]=vl.w;
    }
    __syncthreads();

    int w=t>>5, lane=t&31;
    int g=lane>>2, tg=lane&3;
    const uint32_t* bh = sBh + g*164 + tg;
    const uint32_t* bl = sBl + g*164 + tg;
    const float sc = 0.05590169943749474f;

    #pragma unroll
    for(int rt=0;rt<2;rt++){
        long row0 = rowbase + w*32 + rt*16;
        float acc[8][4];
        #pragma unroll
        for(int i=0;i<8;i++){ acc[i][0]=0.f; acc[i][1]=0.f; acc[i][2]=0.f; acc[i][3]=0.f; }
        const uint2* arow0 = Ag + (row0+g  )*160 + tg;
        const uint2* arow1 = Ag + (row0+g+8)*160 + tg;

        #pragma unroll 4
        for(int kt=0; kt<20; kt++){
            uint2 q0 = arow0[kt*8];
            uint2 q2 = arow0[kt*8+4];
            uint2 q1 = arow1[kt*8];
            uint2 q3 = arow1[kt*8+4];
            uint32_t a0h=__byte_perm(q0.x,q0.y,0x5410), a0l=__byte_perm(q0.x,q0.y,0x7632);
            uint32_t a1h=__byte_perm(q1.x,q1.y,0x5410), a1l=__byte_perm(q1.x,q1.y,0x7632);
            uint32_t a2h=__byte_perm(q2.x,q2.y,0x5410), a2l=__byte_perm(q2.x,q2.y,0x7632);
            uint32_t a3h=__byte_perm(q3.x,q3.y,0x5410), a3l=__byte_perm(q3.x,q3.y,0x7632);
            #pragma unroll
            for(int nt=0;nt<8;nt++){
                int bi = nt*8*164 + kt*8;
                uint32_t b0h=bh[bi],  b1h=bh[bi+4];
                uint32_t b0l=bl[bi],  b1l=bl[bi+4];
                mma16816(acc[nt], a0h,a1h,a2h,a3h, b0h,b1h);
                mma16816(acc[nt], a0h,a1h,a2h,a3h, b0l,b1l);
                mma16816(acc[nt], a0l,a1l,a2l,a3l, b0h,b1h);
            }
        }
        float* c0 = C + (row0+g  )*64 + tg*2;
        float* c1 = C + (row0+g+8)*64 + tg*2;
        #pragma unroll
        for(int nt=0;nt<8;nt++){
            *(float2*)(c0 + nt*8) = make_float2(acc[nt][0]*sc, acc[nt][1]*sc);
            *(float2*)(c1 + nt*8) = make_float2(acc[nt][2]*sc, acc[nt][3]*sc);
        }
    }
}

// ---------------- fused 3-layer MMA MLP (256 thr, 128 edges/block; pad-132/36 B rows) ----------------
#define MLP_SMEM ((2*64*132 + 4*64*36)*4)
__global__ void __launch_bounds__(256) k_mlpmma(float* __restrict__ xout){
    extern __shared__ uint32_t sm[];
    uint32_t* sW1h = sm;                    // [64][132]
    uint32_t* sW1l = sm + 64*132;
    uint32_t* sW2h = sm + 2*64*132;         // [64][36]
    uint32_t* sW2l = sW2h + 64*36;
    uint32_t* sW3h = sW2l + 64*36;
    uint32_t* sW3l = sW3h + 64*36;
    int t=threadIdx.x;
    for(int q=t;q<2048;q+=256){
        uint4 vh=((const uint4*)g_W1h)[q], vl=((const uint4*)g_W1l)[q];
        int w0=q*4, n=w0>>7, p=w0&127, base=n*132+p;
        sW1h[base]=vh.x; sW1h[base+1]=vh.y; sW1h[base+2]=vh.z; sW1h[base+3]=vh.w;
        sW1l[base]=vl.x; sW1l[base+1]=vl.y; sW1l[base+2]=vl.z; sW1l[base+3]=vl.w;
    }
    for(int q=t;q<512;q+=256){
        int w0=q*4, n=w0>>5, p=w0&31, base=n*36+p;
        uint4 v2h=((const uint4*)g_W2h)[q], v2l=((const uint4*)g_W2l)[q];
        uint4 v3h=((const uint4*)g_W3h)[q], v3l=((const uint4*)g_W3l)[q];
        sW2h[base]=v2h.x; sW2h[base+1]=v2h.y; sW2h[base+2]=v2h.z; sW2h[base+3]=v2h.w;
        sW2l[base]=v2l.x; sW2l[base+1]=v2l.y; sW2l[base+2]=v2l.z; sW2l[base+3]=v2l.w;
        sW3h[base]=v3h.x; sW3h[base+1]=v3h.y; sW3h[base+2]=v3h.z; sW3h[base+3]=v3h.w;
        sW3l[base]=v3l.x; sW3l[base+1]=v3l.y; sW3l[base+2]=v3l.z; sW3l[base+3]=v3l.w;
    }
    __syncthreads();

    int w=t>>5, lane=t&31, g=lane>>2, tg=lane&3;
    int e0 = blockIdx.x*128 + w*16;
    float inv_actc = 1.0f/g_actc;

    float acc[8][4];
    #pragma unroll
    for(int i=0;i<8;i++){ acc[i][0]=0.f; acc[i][1]=0.f; acc[i][2]=0.f; acc[i][3]=0.f; }
    const uint2* Ap = (const uint2*)g_hp;
    const uint2* ar0 = Ap + (e0+g  )*128 + tg;
    const uint2* ar1 = Ap + (e0+g+8)*128 + tg;
    #pragma unroll 2
    for(int kt=0;kt<16;kt++){
        uint2 q0=ar0[kt*8],   q2=ar0[kt*8+4];
        uint2 q1=ar1[kt*8],   q3=ar1[kt*8+4];
        uint32_t a0h=__byte_perm(q0.x,q0.y,0x5410), a0l=__byte_perm(q0.x,q0.y,0x7632);
        uint32_t a1h=__byte_perm(q1.x,q1.y,0x5410), a1l=__byte_perm(q1.x,q1.y,0x7632);
        uint32_t a2h=__byte_perm(q2.x,q2.y,0x5410), a2l=__byte_perm(q2.x,q2.y,0x7632);
        uint32_t a3h=__byte_perm(q3.x,q3.y,0x5410), a3l=__byte_perm(q3.x,q3.y,0x7632);
        #pragma unroll
        for(int nt=0;nt<8;nt++){
            int bi=(nt*8+g)*132 + kt*8 + tg;
            uint32_t b0h=sW1h[bi], b1h=sW1h[bi+4];
            uint32_t b0l=sW1l[bi], b1l=sW1l[bi+4];
            mma16816(acc[nt], a0h,a1h,a2h,a3h, b0h,b1h);
            mma16816(acc[nt], a0h,a1h,a2h,a3h, b0l,b1l);
            mma16816(acc[nt], a0l,a1l,a2l,a3l, b0h,b1h);
        }
    }
    float v[8][4];
    #pragma unroll
    for(int nt=0;nt<8;nt++)
        #pragma unroll
        for(int j=0;j<4;j++){
            float a = acc[nt][j]*0.0625f;
            v[nt][j] = a*__fdividef(1.f, 1.f+__expf(-a))*inv_actc;
        }

    #pragma unroll
    for(int i=0;i<8;i++){ acc[i][0]=0.f; acc[i][1]=0.f; acc[i][2]=0.f; acc[i][3]=0.f; }
    #pragma unroll
    for(int kt=0;kt<4;kt++){
        uint32_t a0h,a0l,a1h,a1l,a2h,a2l,a3h,a3l;
        split2(v[2*kt][0],  v[2*kt][1],   a0h,a0l);
        split2(v[2*kt][2],  v[2*kt][3],   a1h,a1l);
        split2(v[2*kt+1][0],v[2*kt+1][1], a2h,a2l);
        split2(v[2*kt+1][2],v[2*kt+1][3], a3h,a3l);
        #pragma unroll
        for(int nt=0;nt<8;nt++){
            int bi=(nt*8+g)*36 + kt*8 + tg;
            uint32_t b0h=sW2h[bi], b1h=sW2h[bi+4];
            uint32_t b0l=sW2l[bi], b1l=sW2l[bi+4];
            mma16816(acc[nt], a0h,a1h,a2h,a3h, b0h,b1h);
            mma16816(acc[nt], a0h,a1h,a2h,a3h, b0l,b1l);
            mma16816(acc[nt], a0l,a1l,a2l,a3l, b0h,b1h);
        }
    }
    #pragma unroll
    for(int nt=0;nt<8;nt++)
        #pragma unroll
        for(int j=0;j<4;j++){
            float a = acc[nt][j]*0.125f;
            v[nt][j] = a*__fdividef(1.f, 1.f+__expf(-a))*inv_actc;
        }

    #pragma unroll
    for(int i=0;i<8;i++){ acc[i][0]=0.f; acc[i][1]=0.f; acc[i][2]=0.f; acc[i][3]=0.f; }
    #pragma unroll
    for(int kt=0;kt<4;kt++){
        uint32_t a0h,a0l,a1h,a1l,a2h,a2l,a3h,a3l;
        split2(v[2*kt][0],  v[2*kt][1],   a0h,a0l);
        split2(v[2*kt][2],  v[2*kt][3],   a1h,a1l);
        split2(v[2*kt+1][0],v[2*kt+1][1], a2h,a2l);
        split2(v[2*kt+1][2],v[2*kt+1][3], a3h,a3l);
        #pragma unroll
        for(int nt=0;nt<8;nt++){
            int bi=(nt*8+g)*36 + kt*8 + tg;
            uint32_t b0h=sW3h[bi], b1h=sW3h[bi+4];
            uint32_t b0l=sW3l[bi], b1l=sW3l[bi+4];
            mma16816(acc[nt], a0h,a1h,a2h,a3h, b0h,b1h);
            mma16816(acc[nt], a0h,a1h,a2h,a3h, b0l,b1l);
            mma16816(acc[nt], a0l,a1l,a2l,a3l, b0h,b1h);
        }
    }

    int eg0=e0+g, eg1=e0+g+8;
    float d0=g_d[eg0], d1=g_d[eg1];
    float f0=0.f, f1=0.f;
    if(d0<1.f){ float d3=d0*d0*d0, d6=d3*d3, d7=d6*d0, d8=d7*d0; f0=(1.f-28.f*d6+48.f*d7-21.f*d8)*0.125f; }
    if(d1<1.f){ float d3=d1*d1*d1, d6=d3*d3, d7=d6*d1, d8=d7*d1; f1=(1.f-28.f*d6+48.f*d7-21.f*d8)*0.125f; }
    float* o0 = xout + eg0*64 + tg*2;
    float* o1 = xout + eg1*64 + tg*2;
    #pragma unroll
    for(int nt=0;nt<8;nt++){
        *(float2*)(o0 + nt*8) = make_float2(acc[nt][0]*f0, acc[nt][1]*f0);
        *(float2*)(o1 + nt*8) = make_float2(acc[nt][2]*f1, acc[nt][3]*f1);
    }
}

// ---------------- interleave staging -> V_out layout (pad-65 rows, conflict-free) ----------------
__global__ void k_pack(float* __restrict__ vout){
    __shared__ float sC1[48*65];
    __shared__ float sC2[80*65];
    int t=threadIdx.x; long e0 = (long)blockIdx.x*16;
    const float4* c1 = (const float4*)(g_C1 + e0*3*64);
    const float4* c2 = (const float4*)(g_C2 + e0*5*64);
    for(int q=t;q<768;q+=256){
        float4 v=c1[q];
        int w0=q*4, r=w0>>6, p=w0&63, base=r*65+p;
        sC1[base]=v.x; sC1[base+1]=v.y; sC1[base+2]=v.z; sC1[base+3]=v.w;
    }
    for(int q=t;q<1280;q+=256){
        float4 v=c2[q];
        int w0=q*4, r=w0>>6, p=w0&63, base=r*65+p;
        sC2[base]=v.x; sC2[base+1]=v.y; sC2[base+2]=v.z; sC2[base+3]=v.w;
    }
    __syncthreads();
    for(int le=0;le<16;le++){
        float* op = vout + (e0+le)*576;
        #pragma unroll
        for(int pass=0;pass<3;pass++){
            int off = t + pass*256;
            if(off<576){
                int o = off/9, c = off - o*9;
                float v = 0.f;
                if(c>=1 && c<4)      v = sC1[(le*3 + c-1)*65 + o];
                else if(c>=4)        v = sC2[(le*5 + c-4)*65 + o];
                op[off]=v;
            }
        }
    }
}

// ---------------- launch ----------------
extern "C" void kernel_launch(void* const* d_in, const int* in_sizes, int n_in,
                              void* d_out, int out_size){
    const float* vectors = (const float*)d_in[0];
    const float* x       = (const float*)d_in[1];
    const float* V       = (const float*)d_in[2];
    const int*   senders = (const int*)  d_in[3];
    const float* Ww      = (const float*)d_in[4];
    const float* W1      = (const float*)d_in[5];
    const float* W2      = (const float*)d_in[6];
    const float* W3      = (const float*)d_in[7];
    const float* Wv1     = (const float*)d_in[8];
    const float* Wv2     = (const float*)d_in[9];
    float* out  = (float*)d_out;
    float* vout = out + (size_t)NE*64;

    host_compute_constants();
    cudaMemcpyToSymbolAsync(g_cg,   s_cg_host,    sizeof(s_cg_host), 0, cudaMemcpyHostToDevice, 0);
    cudaMemcpyToSymbolAsync(g_actc, &s_actc_host, sizeof(float),     0, cudaMemcpyHostToDevice, 0);

    cudaFuncSetAttribute(k_gemm,   cudaFuncAttributeMaxDynamicSharedMemorySize, GEMM_SMEM);
    cudaFuncSetAttribute(k_mlpmma, cudaFuncAttributeMaxDynamicSharedMemorySize, MLP_SMEM);

    k_prep<<<PREP_WPACK_BLOCKS + NE/4,256>>>(Wv1, Wv2, W1, W2, W3, Ww, x, vectors, senders);
    k_wmma<<<NE/128,256>>>();
    k_scan<<<1,1024>>>();
    k_fill<<<64,256>>>(senders);
    k_gather<<<NNODES/4,128>>>();
    k_tp<<<NE/8,256>>>(V, senders);
    k_gemm<<<(NE*8)/256,256,GEMM_SMEM>>>();
    k_mlpmma<<<NE/128,256,MLP_SMEM>>>(out);
    k_pack<<<NE/16,256>>>(vout);
}